// round 13
// baseline (speedup 1.0000x reference)
#include <cuda_runtime.h>
#include <cuda_fp16.h>
#include <math.h>
#include <stdint.h>

#define B_  4
#define T_  1024
#define E_  1024
#define H_  16
#define HD  64
#define L_  6
#define FF_ 4096
#define V_  32000
#define BT  (B_ * T_)
#define E3  (3 * E_)

#define SZ_EE ((size_t)E_ * E_)
#define OQKV  ((size_t)0)
#define OWO   ((size_t)18 * SZ_EE)
#define OW1   ((size_t)24 * SZ_EE)
#define OW2   ((size_t)48 * SZ_EE)
#define OHEAD ((size_t)72 * SZ_EE)
#define WTOT  (OHEAD + (size_t)E_ * V_)

// ---------------- device scratch ----------------
__device__ float  g_x[BT * E_];
__device__ __half g_xr[BT * E_];
__device__ __half g_qkvh[(size_t)BT * E3];   // fp16 QKV (flash input)
__device__ float  g_tmp[BT * E_];
__device__ __half g_ffr[(size_t)BT * FF_];
__device__ float  g_bqkv[L_ * E3];
__device__ __half g_wt[WTOT];

// ---------------- helpers ----------------
__device__ __forceinline__ uint32_t smem_u32(const void* p) {
    uint32_t a;
    asm("{ .reg .u64 t; cvta.to.shared.u64 t, %1; cvt.u32.u64 %0, t; }" : "=r"(a) : "l"(p));
    return a;
}
__device__ __forceinline__ float warpSum(float v) {
    #pragma unroll
    for (int o = 16; o > 0; o >>= 1) v += __shfl_xor_sync(0xffffffffu, v, o);
    return v;
}
__device__ __forceinline__ void ldsm4(uint32_t* r, uint32_t addr) {
    asm volatile("ldmatrix.sync.aligned.m8n8.x4.shared.b16 {%0,%1,%2,%3}, [%4];"
                 : "=r"(r[0]), "=r"(r[1]), "=r"(r[2]), "=r"(r[3]) : "r"(addr));
}
__device__ __forceinline__ void ldsm4t(uint32_t* r, uint32_t addr) {
    asm volatile("ldmatrix.sync.aligned.m8n8.x4.trans.shared.b16 {%0,%1,%2,%3}, [%4];"
                 : "=r"(r[0]), "=r"(r[1]), "=r"(r[2]), "=r"(r[3]) : "r"(addr));
}
__device__ __forceinline__ void cpa16(uint32_t dst, const void* src) {
    asm volatile("cp.async.cg.shared.global [%0], [%1], 16;" :: "r"(dst), "l"(src));
}
__device__ __forceinline__ void mma_f16(float* c, const uint32_t* a, uint32_t b0, uint32_t b1) {
    asm volatile(
        "mma.sync.aligned.m16n8k16.row.col.f32.f16.f16.f32 "
        "{%0,%1,%2,%3}, {%4,%5,%6,%7}, {%8,%9}, {%0,%1,%2,%3};\n"
        : "+f"(c[0]), "+f"(c[1]), "+f"(c[2]), "+f"(c[3])
        : "r"(a[0]), "r"(a[1]), "r"(a[2]), "r"(a[3]), "r"(b0), "r"(b1));
}

// ---------------- embedding ----------------
__global__ void embed_kernel(const int* __restrict__ idx,
                             const float* __restrict__ tok,
                             const float* __restrict__ pos,
                             float* __restrict__ x,
                             __half* __restrict__ xr) {
    int bt = blockIdx.x;
    int t  = bt & (T_ - 1);
    int id = idx[bt];
    int c  = threadIdx.x;
    float4 a = ((const float4*)(tok + (size_t)id * E_))[c];
    float4 p = ((const float4*)(pos + (size_t)t  * E_))[c];
    a.x += p.x; a.y += p.y; a.z += p.z; a.w += p.w;
    ((float4*)(x + (size_t)bt * E_))[c] = a;
    __half2 h0 = __floats2half2_rn(a.x, a.y);
    __half2 h1 = __floats2half2_rn(a.z, a.w);
    uint2 u; u.x = *(uint32_t*)&h0; u.y = *(uint32_t*)&h1;
    ((uint2*)(xr + (size_t)bt * E_))[c] = u;
}

// ---------------- bias pack ----------------
__global__ void pack_bias_kernel(const float* __restrict__ bq,
                                 const float* __restrict__ bk,
                                 const float* __restrict__ bv,
                                 float* __restrict__ o) {
    int l = blockIdx.y;
    int i = blockIdx.x * 256 + threadIdx.x;
    int w = i >> 10, c = i & 1023;
    const float* s = (w == 0) ? bq : (w == 1) ? bk : bv;
    o[l * E3 + i] = s[l * E_ + c];
}

// ---------------- weight transpose + fp16 round (vectorized) ----------------
// W: [K,N] f32 -> To [N][K] fp16. 32x32 tiles, float4 in / uint2 (4x fp16) out.
__global__ void tconv_kernel(const float* __restrict__ W,
                             __half* __restrict__ To,
                             int K, int N, size_t lso) {
    __shared__ float tile[32][33];
    const float* Wl = W + (size_t)blockIdx.z * K * N;
    __half* Tol = To + (size_t)blockIdx.z * lso;
    int n0 = blockIdx.x * 32, k0 = blockIdx.y * 32;
    int tid = threadIdx.x;          // 256
    int row = tid >> 3;             // 0..31
    int c4  = (tid & 7) * 4;        // 0,4,...,28

    float4 v = *(const float4*)(Wl + (size_t)(k0 + row) * N + n0 + c4);
    tile[row][c4 + 0] = v.x; tile[row][c4 + 1] = v.y;
    tile[row][c4 + 2] = v.z; tile[row][c4 + 3] = v.w;
    __syncthreads();

    // write 4 consecutive k for output row n = n0 + row
    __half2 ha = __halves2half2(__float2half_rn(tile[c4 + 0][row]),
                                __float2half_rn(tile[c4 + 1][row]));
    __half2 hb = __halves2half2(__float2half_rn(tile[c4 + 2][row]),
                                __float2half_rn(tile[c4 + 3][row]));
    uint2 u; u.x = *(uint32_t*)&ha; u.y = *(uint32_t*)&hb;
    *(uint2*)(Tol + (size_t)(n0 + row) * K + k0 + c4) = u;
}

// ================= fp16 GEMM: 128x128 CTA, K-chunk 64, 3 buffers, 2 CTAs/SM ==========
// Single-barrier multistage mainloop (prefetch depth 2). MODE: 0 fp32 out, 2 fp16 out.
#define STP 128
#define STT (128 * STP)
#define STB (2 * STT)
#define GSM (3 * STB)

template<int RELU, int MODE>
__global__ __launch_bounds__(256, 2)
void h16_gemm_kernel(const __half* __restrict__ A, const __half* __restrict__ Bt,
                     const float* __restrict__ bias,
                     float* __restrict__ Cf, __half* __restrict__ Ch,
                     int M, int N, int K) {
    extern __shared__ char smem_raw[];
    uint32_t sb = smem_u32(smem_raw);

    int tid = threadIdx.x, wid = tid >> 5, lane = tid & 31;
    int g = lane >> 2, tq = lane & 3;
    int wm = (wid >> 2) * 64;
    int wn = (wid & 3) * 32;
    int bm = blockIdx.y * 128, bn = blockIdx.x * 128;

    const __half* baseA = A  + (size_t)bm * K;
    const __half* baseB = Bt + (size_t)bn * K;
    int nch = K / 64;

    auto load_chunk = [&](int ci, int s) {
        uint32_t st = sb + s * STB;
        int k0 = ci * 64;
        #pragma unroll
        for (int j = 0; j < 8; j++) {
            int seg  = tid + j * 256;
            int tens = seg >> 10;
            int rem  = seg & 1023;
            int row  = rem >> 3;
            int c    = rem & 7;
            uint32_t dst = st + tens * STT + row * STP + ((c ^ (row & 7)) << 4);
            const __half* src = (tens ? baseB : baseA) + (size_t)row * K + k0 + c * 8;
            cpa16(dst, src);
        }
        asm volatile("cp.async.commit_group;" ::: "memory");
    };

    float acc[4][4][4];
    #pragma unroll
    for (int a = 0; a < 4; a++)
        #pragma unroll
        for (int b = 0; b < 4; b++)
            #pragma unroll
            for (int c = 0; c < 4; c++) acc[a][b][c] = 0.f;

    load_chunk(0, 0);
    load_chunk(1, 1);

    int arow_l = lane & 15;
    int acb    = lane >> 4;
    int brow_l = (lane & 7) + ((lane >> 4) << 3);
    int bcb    = (lane >> 3) & 1;

    for (int i = 0; i < nch; i++) {
        if (i < nch - 1) asm volatile("cp.async.wait_group 1;" ::: "memory");
        else             asm volatile("cp.async.wait_group 0;" ::: "memory");
        __syncthreads();
        if (i + 2 < nch) load_chunk(i + 2, (i + 2) % 3);   // writes stage consumed at iter i-1

        uint32_t stA = sb + (i % 3) * STB;
        uint32_t stB = stA + STT;

        #pragma unroll
        for (int kk = 0; kk < 4; kk++) {
            uint32_t af[4][4], bf[2][4];
            #pragma unroll
            for (int mi = 0; mi < 4; mi++) {
                int r = wm + mi * 16 + arow_l;
                int c = kk * 2 + acb;
                ldsm4(af[mi], stA + r * STP + ((c ^ (r & 7)) << 4));
            }
            #pragma unroll
            for (int nb = 0; nb < 2; nb++) {
                int r = wn + nb * 16 + brow_l;
                int c = kk * 2 + bcb;
                ldsm4(bf[nb], stB + r * STP + ((c ^ (r & 7)) << 4));
            }
            #pragma unroll
            for (int mi = 0; mi < 4; mi++)
                #pragma unroll
                for (int ni = 0; ni < 4; ni++) {
                    int nb = ni >> 1, o = (ni & 1) * 2;
                    mma_f16(acc[mi][ni], af[mi], bf[nb][o], bf[nb][o + 1]);
                }
        }
        // no trailing barrier: next iteration's top barrier orders stage reuse
    }

    #pragma unroll
    for (int mi = 0; mi < 4; mi++) {
        int r0 = bm + wm + mi * 16 + g;
        #pragma unroll
        for (int ni = 0; ni < 4; ni++) {
            int c0 = bn + wn + ni * 8 + 2 * tq;
            float bx = bias[c0], by = bias[c0 + 1];
            float2 v0, v1;
            v0.x = acc[mi][ni][0] + bx; v0.y = acc[mi][ni][1] + by;
            v1.x = acc[mi][ni][2] + bx; v1.y = acc[mi][ni][3] + by;
            if (RELU) {
                v0.x = fmaxf(v0.x, 0.f); v0.y = fmaxf(v0.y, 0.f);
                v1.x = fmaxf(v1.x, 0.f); v1.y = fmaxf(v1.y, 0.f);
            }
            if (MODE == 0) {
                *(float2*)(Cf + (size_t)r0 * N + c0)       = v0;
                *(float2*)(Cf + (size_t)(r0 + 8) * N + c0) = v1;
            } else {
                __half2 h0 = __floats2half2_rn(v0.x, v0.y);
                __half2 h1 = __floats2half2_rn(v1.x, v1.y);
                *(__half2*)(Ch + (size_t)r0 * N + c0)       = h0;
                *(__half2*)(Ch + (size_t)(r0 + 8) * N + c0) = h1;
            }
        }
    }
}

// ================= fused flash attention (fp16 mma) =================
#define FPH 72
#define FHB (FPH * 2)
#define HT_BYTES (64 * FHB)
#define FSMEM (4 * HT_BYTES)

__global__ __launch_bounds__(128)
void flash_kernel(const __half* __restrict__ qkv, __half* __restrict__ xr) {
    extern __shared__ __align__(16) char fsm[];
    uint32_t sbQ = smem_u32(fsm);
    uint32_t sbK = sbQ + HT_BYTES;
    uint32_t sbV = sbK + HT_BYTES;
    uint32_t sbP = sbV + HT_BYTES;
    __half* Psp = (__half*)(fsm + 3 * HT_BYTES);

    int it = (int)gridDim.x - 1 - (int)blockIdx.x;
    int bh = blockIdx.y;
    int b = bh >> 4, h = bh & 15;
    int tid = threadIdx.x, wid = tid >> 5, lane = tid & 31;
    int g = lane >> 2, tq = lane & 3;
    int wm = wid * 16;

    int arow_l = lane & 15;
    int acb    = lane >> 4;
    int brow_l = (lane & 7) + ((lane >> 4) << 3);
    int bcb    = (lane >> 3) & 1;
    int jrow   = (lane & 7) + ((lane >> 3) & 1) * 8;
    int dcol   = (lane >> 4) * 8;

    const __half* qbase = qkv + (size_t)(b * T_ + it * 64) * E3 + h * HD;
    #pragma unroll
    for (int p = 0; p < 4; p++) {
        int seg = tid + p * 128;
        int r = seg >> 3, c = seg & 7;
        cpa16(sbQ + (uint32_t)(r * FHB + c * 16), qbase + (size_t)r * E3 + c * 8);
    }
    asm volatile("cp.async.commit_group;" ::: "memory");
    asm volatile("cp.async.wait_group 0;" ::: "memory");
    __syncthreads();

    uint32_t qf[4][4];
    #pragma unroll
    for (int kk = 0; kk < 4; kk++)
        ldsm4(qf[kk], sbQ + (uint32_t)((wm + arow_l) * FHB + (kk * 16 + acb * 8) * 2));

    float m0 = -1e30f, m1 = -1e30f, l0 = 0.f, l1 = 0.f;
    float oac[8][4];
    #pragma unroll
    for (int n = 0; n < 8; n++)
        #pragma unroll
        for (int c = 0; c < 4; c++) oac[n][c] = 0.f;

    const __half* kbase = qkv + (size_t)(b * T_) * E3 + E_     + h * HD;
    const __half* vbase = qkv + (size_t)(b * T_) * E3 + 2 * E_ + h * HD;

    for (int jt = 0; jt <= it; jt++) {
        const __half* kb = kbase + (size_t)jt * 64 * E3;
        const __half* vb = vbase + (size_t)jt * 64 * E3;
        #pragma unroll
        for (int p = 0; p < 4; p++) {
            int seg = tid + p * 128;
            int r = seg >> 3, c = seg & 7;
            cpa16(sbK + (uint32_t)(r * FHB + c * 16), kb + (size_t)r * E3 + c * 8);
            cpa16(sbV + (uint32_t)(r * FHB + c * 16), vb + (size_t)r * E3 + c * 8);
        }
        asm volatile("cp.async.commit_group;" ::: "memory");
        asm volatile("cp.async.wait_group 0;" ::: "memory");
        __syncthreads();

        float sac[8][4];
        #pragma unroll
        for (int n = 0; n < 8; n++)
            #pragma unroll
            for (int c = 0; c < 4; c++) sac[n][c] = 0.f;
        #pragma unroll
        for (int kk = 0; kk < 4; kk++) {
            uint32_t bfK[4][4];
            #pragma unroll
            for (int nb = 0; nb < 4; nb++)
                ldsm4(bfK[nb], sbK + (uint32_t)((nb * 16 + brow_l) * FHB + (kk * 16 + bcb * 8) * 2));
            #pragma unroll
            for (int ni = 0; ni < 8; ni++) {
                int nb = ni >> 1, o = (ni & 1) * 2;
                mma_f16(sac[ni], qf[kk], bfK[nb][o], bfK[nb][o + 1]);
            }
        }

        #pragma unroll
        for (int ni = 0; ni < 8; ni++) {
            sac[ni][0] *= 0.125f; sac[ni][1] *= 0.125f;
            sac[ni][2] *= 0.125f; sac[ni][3] *= 0.125f;
        }
        if (jt == it) {
            #pragma unroll
            for (int ni = 0; ni < 8; ni++) {
                int cb = ni * 8 + 2 * tq;
                int r0 = wm + g, r1 = wm + g + 8;
                if (cb     > r0) sac[ni][0] = -1e30f;
                if (cb + 1 > r0) sac[ni][1] = -1e30f;
                if (cb     > r1) sac[ni][2] = -1e30f;
                if (cb + 1 > r1) sac[ni][3] = -1e30f;
            }
        }
        float a0 = -1e30f, a1 = -1e30f;
        #pragma unroll
        for (int ni = 0; ni < 8; ni++) {
            a0 = fmaxf(a0, fmaxf(sac[ni][0], sac[ni][1]));
            a1 = fmaxf(a1, fmaxf(sac[ni][2], sac[ni][3]));
        }
        a0 = fmaxf(a0, __shfl_xor_sync(0xffffffffu, a0, 1));
        a0 = fmaxf(a0, __shfl_xor_sync(0xffffffffu, a0, 2));
        a1 = fmaxf(a1, __shfl_xor_sync(0xffffffffu, a1, 1));
        a1 = fmaxf(a1, __shfl_xor_sync(0xffffffffu, a1, 2));
        float mn0 = fmaxf(m0, a0), mn1 = fmaxf(m1, a1);
        float al0 = __expf(m0 - mn0), al1 = __expf(m1 - mn1);
        m0 = mn0; m1 = mn1;
        l0 *= al0; l1 *= al1;
        #pragma unroll
        for (int ni = 0; ni < 8; ni++) {
            oac[ni][0] *= al0; oac[ni][1] *= al0;
            oac[ni][2] *= al1; oac[ni][3] *= al1;
        }
        float s0 = 0.f, s1 = 0.f;
        #pragma unroll
        for (int ni = 0; ni < 8; ni++) {
            __half2 hp0 = __floats2half2_rn(__expf(sac[ni][0] - mn0), __expf(sac[ni][1] - mn0));
            __half2 hp1 = __floats2half2_rn(__expf(sac[ni][2] - mn1), __expf(sac[ni][3] - mn1));
            s0 += __low2float(hp0) + __high2float(hp0);
            s1 += __low2float(hp1) + __high2float(hp1);
            int cb = ni * 8 + 2 * tq;
            *(__half2*)(Psp + (wm + g) * FPH + cb)     = hp0;
            *(__half2*)(Psp + (wm + g + 8) * FPH + cb) = hp1;
        }
        s0 += __shfl_xor_sync(0xffffffffu, s0, 1);
        s0 += __shfl_xor_sync(0xffffffffu, s0, 2);
        s1 += __shfl_xor_sync(0xffffffffu, s1, 1);
        s1 += __shfl_xor_sync(0xffffffffu, s1, 2);
        l0 += s0; l1 += s1;
        __syncwarp();

        #pragma unroll
        for (int jb = 0; jb < 4; jb++) {
            uint32_t pf[4];
            ldsm4(pf, sbP + (uint32_t)((wm + arow_l) * FHB + (jb * 16 + acb * 8) * 2));
            #pragma unroll
            for (int db = 0; db < 4; db++) {
                uint32_t vf[4];
                ldsm4t(vf, sbV + (uint32_t)((jb * 16 + jrow) * FHB + (db * 16 + dcol) * 2));
                mma_f16(oac[db * 2],     pf, vf[0], vf[1]);
                mma_f16(oac[db * 2 + 1], pf, vf[2], vf[3]);
            }
        }
        __syncthreads();
    }

    float inv0 = 1.f / l0, inv1 = 1.f / l1;
    __half* od = xr + (size_t)(b * T_ + it * 64 + wm + g) * E_ + h * HD;
    #pragma unroll
    for (int nd = 0; nd < 8; nd++) {
        int cb = nd * 8 + 2 * tq;
        __half2 v0 = __floats2half2_rn(oac[nd][0] * inv0, oac[nd][1] * inv0);
        __half2 v1 = __floats2half2_rn(oac[nd][2] * inv1, oac[nd][3] * inv1);
        *(__half2*)(od + cb)                  = v0;
        *(__half2*)(od + (size_t)8 * E_ + cb) = v1;
    }
}

// ---------------- out = LayerNorm(in (+ res)) ----------------
__global__ void add_ln_kernel(const float* __restrict__ in,
                              const float* __restrict__ res,
                              const float* __restrict__ g,
                              const float* __restrict__ bb,
                              float* __restrict__ out,
                              __half* __restrict__ outr) {
    int row = blockIdx.x;
    int t = threadIdx.x;
    float4 v = ((const float4*)(in + (size_t)row * E_))[t];
    if (res) {
        float4 r = ((const float4*)(res + (size_t)row * E_))[t];
        v.x += r.x; v.y += r.y; v.z += r.z; v.w += r.w;
    }
    float s  = v.x + v.y + v.z + v.w;
    float s2 = v.x * v.x + v.y * v.y + v.z * v.z + v.w * v.w;

    __shared__ float sh[16];
    s = warpSum(s); s2 = warpSum(s2);
    int w = t >> 5, lane = t & 31;
    if (lane == 0) { sh[w] = s; sh[w + 8] = s2; }
    __syncthreads();
    if (w == 0) {
        float a  = (lane < 8) ? sh[lane] : 0.f;
        a = warpSum(a);
        float a2 = (lane < 8) ? sh[lane + 8] : 0.f;
        a2 = warpSum(a2);
        if (lane == 0) { sh[0] = a; sh[8] = a2; }
    }
    __syncthreads();
    float mean = sh[0] * (1.f / E_);
    float var  = sh[8] * (1.f / E_) - mean * mean;
    float rstd = rsqrtf(var + 1e-5f);

    float4 gv = ((const float4*)g)[t];
    float4 bv = ((const float4*)bb)[t];
    float4 o;
    o.x = (v.x - mean) * rstd * gv.x + bv.x;
    o.y = (v.y - mean) * rstd * gv.y + bv.y;
    o.z = (v.z - mean) * rstd * gv.z + bv.z;
    o.w = (v.w - mean) * rstd * gv.w + bv.w;
    ((float4*)(out + (size_t)row * E_))[t] = o;

    __half2 h0 = __floats2half2_rn(o.x, o.y);
    __half2 h1 = __floats2half2_rn(o.z, o.w);
    uint2 u; u.x = *(uint32_t*)&h0; u.y = *(uint32_t*)&h1;
    ((uint2*)(outr + (size_t)row * E_))[t] = u;
}

// ---------------- host launch ----------------
extern "C" void kernel_launch(void* const* d_in, const int* in_sizes, int n_in,
                              void* d_out, int out_size) {
    const int*   idx   = (const int*)  d_in[0];
    const float* tok   = (const float*)d_in[1];
    const float* pos   = (const float*)d_in[2];
    const float* Wq    = (const float*)d_in[3];
    const float* bq    = (const float*)d_in[4];
    const float* Wk    = (const float*)d_in[5];
    const float* bk    = (const float*)d_in[6];
    const float* Wv    = (const float*)d_in[7];
    const float* bv    = (const float*)d_in[8];
    const float* Wo    = (const float*)d_in[9];
    const float* bo    = (const float*)d_in[10];
    const float* W1    = (const float*)d_in[11];
    const float* b1    = (const float*)d_in[12];
    const float* W2    = (const float*)d_in[13];
    const float* b2    = (const float*)d_in[14];
    const float* ln1g  = (const float*)d_in[15];
    const float* ln1b  = (const float*)d_in[16];
    const float* ln2g  = (const float*)d_in[17];
    const float* ln2b  = (const float*)d_in[18];
    const float* lnfg  = (const float*)d_in[19];
    const float* lnfb  = (const float*)d_in[20];
    const float* Whead = (const float*)d_in[21];
    const float* bhead = (const float*)d_in[22];
    float* out = (float*)d_out;

    float *x, *tmp, *bqkv;
    __half *xr, *qkvh, *ffr, *wt;
    cudaGetSymbolAddress((void**)&x,    g_x);
    cudaGetSymbolAddress((void**)&xr,   g_xr);
    cudaGetSymbolAddress((void**)&qkvh, g_qkvh);
    cudaGetSymbolAddress((void**)&tmp,  g_tmp);
    cudaGetSymbolAddress((void**)&ffr,  g_ffr);
    cudaGetSymbolAddress((void**)&bqkv, g_bqkv);
    cudaGetSymbolAddress((void**)&wt,   g_wt);

    cudaFuncSetAttribute(h16_gemm_kernel<0,0>,
                         cudaFuncAttributeMaxDynamicSharedMemorySize, GSM);
    cudaFuncSetAttribute(h16_gemm_kernel<0,2>,
                         cudaFuncAttributeMaxDynamicSharedMemorySize, GSM);
    cudaFuncSetAttribute(h16_gemm_kernel<1,2>,
                         cudaFuncAttributeMaxDynamicSharedMemorySize, GSM);
    cudaFuncSetAttribute(flash_kernel,
                         cudaFuncAttributeMaxDynamicSharedMemorySize, FSMEM);

    tconv_kernel<<<dim3(E_ / 32,  E_ / 32,  L_), 256>>>(Wq, wt + OQKV,             E_, E_, 3 * SZ_EE);
    tconv_kernel<<<dim3(E_ / 32,  E_ / 32,  L_), 256>>>(Wk, wt + OQKV + SZ_EE,     E_, E_, 3 * SZ_EE);
    tconv_kernel<<<dim3(E_ / 32,  E_ / 32,  L_), 256>>>(Wv, wt + OQKV + 2 * SZ_EE, E_, E_, 3 * SZ_EE);
    tconv_kernel<<<dim3(E_ / 32,  E_ / 32,  L_), 256>>>(Wo, wt + OWO,  E_,  E_,  SZ_EE);
    tconv_kernel<<<dim3(FF_ / 32, E_ / 32,  L_), 256>>>(W1, wt + OW1,  E_,  FF_, (size_t)E_ * FF_);
    tconv_kernel<<<dim3(E_ / 32,  FF_ / 32, L_), 256>>>(W2, wt + OW2,  FF_, E_,  (size_t)E_ * FF_);
    tconv_kernel<<<dim3(V_ / 32,  E_ / 32,  1 ), 256>>>(Whead, wt + OHEAD, E_, V_, 0);
    pack_bias_kernel<<<dim3(12, L_), 256>>>(bq, bk, bv, bqkv);

    embed_kernel<<<BT, 256>>>(idx, tok, pos, x, xr);

    dim3 gQKV(E3 / 128, BT / 128);
    dim3 gEE(E_ / 128, BT / 128);
    dim3 gEF(FF_ / 128, BT / 128);
    dim3 gHead(V_ / 128, BT / 128);

    for (int l = 0; l < L_; l++) {
        h16_gemm_kernel<0,2><<<gQKV, 256, GSM>>>(
            xr, wt + OQKV + (size_t)l * 3 * SZ_EE, bqkv + l * E3,
            nullptr, qkvh, BT, E3, E_);

        flash_kernel<<<dim3(16, B_ * H_), 128, FSMEM>>>(qkvh, xr);

        h16_gemm_kernel<0,0><<<gEE, 256, GSM>>>(
            xr, wt + OWO + (size_t)l * SZ_EE, bo + l * E_,
            tmp, nullptr, BT, E_, E_);
        add_ln_kernel<<<BT, 256>>>(x, tmp, ln1g + l * E_, ln1b + l * E_, x, xr);

        h16_gemm_kernel<1,2><<<gEF, 256, GSM>>>(
            xr, wt + OW1 + (size_t)l * E_ * FF_, b1 + l * FF_,
            nullptr, ffr, BT, FF_, E_);
        h16_gemm_kernel<0,0><<<gEE, 256, GSM>>>(
            ffr, wt + OW2 + (size_t)l * E_ * FF_, b2 + l * E_,
            tmp, nullptr, BT, E_, FF_);
        add_ln_kernel<<<BT, 256>>>(x, tmp, ln2g + l * E_, ln2b + l * E_, x, xr);
    }

    add_ln_kernel<<<BT, 256>>>(x, nullptr, lnfg, lnfb, x, xr);
    h16_gemm_kernel<0,0><<<gHead, 256, GSM>>>(
        xr, wt + OHEAD, bhead, out, nullptr, BT, V_, E_);
}

// round 14
// speedup vs baseline: 1.0318x; 1.0318x over previous
#include <cuda_runtime.h>
#include <cuda_fp16.h>
#include <math.h>
#include <stdint.h>

#define B_  4
#define T_  1024
#define E_  1024
#define H_  16
#define HD  64
#define L_  6
#define FF_ 4096
#define V_  32000
#define BT  (B_ * T_)
#define E3  (3 * E_)

#define SZ_EE ((size_t)E_ * E_)
#define OQKV  ((size_t)0)
#define OWO   ((size_t)18 * SZ_EE)
#define OW1   ((size_t)24 * SZ_EE)
#define OW2   ((size_t)48 * SZ_EE)
#define OHEAD ((size_t)72 * SZ_EE)
#define WTOT  (OHEAD + (size_t)E_ * V_)

// ---------------- device scratch ----------------
__device__ float  g_x[BT * E_];
__device__ __half g_xr[BT * E_];
__device__ __half g_qkvh[(size_t)BT * E3];   // fp16 QKV (flash input)
__device__ float  g_tmp[BT * E_];
__device__ __half g_ffr[(size_t)BT * FF_];
__device__ float  g_bqkv[L_ * E3];
__device__ __half g_wt[WTOT];

// ---------------- helpers ----------------
__device__ __forceinline__ uint32_t smem_u32(const void* p) {
    uint32_t a;
    asm("{ .reg .u64 t; cvta.to.shared.u64 t, %1; cvt.u32.u64 %0, t; }" : "=r"(a) : "l"(p));
    return a;
}
__device__ __forceinline__ float warpSum(float v) {
    #pragma unroll
    for (int o = 16; o > 0; o >>= 1) v += __shfl_xor_sync(0xffffffffu, v, o);
    return v;
}
__device__ __forceinline__ void ldsm4(uint32_t* r, uint32_t addr) {
    asm volatile("ldmatrix.sync.aligned.m8n8.x4.shared.b16 {%0,%1,%2,%3}, [%4];"
                 : "=r"(r[0]), "=r"(r[1]), "=r"(r[2]), "=r"(r[3]) : "r"(addr));
}
__device__ __forceinline__ void ldsm4t(uint32_t* r, uint32_t addr) {
    asm volatile("ldmatrix.sync.aligned.m8n8.x4.trans.shared.b16 {%0,%1,%2,%3}, [%4];"
                 : "=r"(r[0]), "=r"(r[1]), "=r"(r[2]), "=r"(r[3]) : "r"(addr));
}
__device__ __forceinline__ void cpa16(uint32_t dst, const void* src) {
    asm volatile("cp.async.cg.shared.global [%0], [%1], 16;" :: "r"(dst), "l"(src));
}
__device__ __forceinline__ void mma_f16(float* c, const uint32_t* a, uint32_t b0, uint32_t b1) {
    asm volatile(
        "mma.sync.aligned.m16n8k16.row.col.f32.f16.f16.f32 "
        "{%0,%1,%2,%3}, {%4,%5,%6,%7}, {%8,%9}, {%0,%1,%2,%3};\n"
        : "+f"(c[0]), "+f"(c[1]), "+f"(c[2]), "+f"(c[3])
        : "r"(a[0]), "r"(a[1]), "r"(a[2]), "r"(a[3]), "r"(b0), "r"(b1));
}

// ---------------- embedding ----------------
__global__ void embed_kernel(const int* __restrict__ idx,
                             const float* __restrict__ tok,
                             const float* __restrict__ pos,
                             float* __restrict__ x,
                             __half* __restrict__ xr) {
    int bt = blockIdx.x;
    int t  = bt & (T_ - 1);
    int id = idx[bt];
    int c  = threadIdx.x;
    float4 a = ((const float4*)(tok + (size_t)id * E_))[c];
    float4 p = ((const float4*)(pos + (size_t)t  * E_))[c];
    a.x += p.x; a.y += p.y; a.z += p.z; a.w += p.w;
    ((float4*)(x + (size_t)bt * E_))[c] = a;
    __half2 h0 = __floats2half2_rn(a.x, a.y);
    __half2 h1 = __floats2half2_rn(a.z, a.w);
    uint2 u; u.x = *(uint32_t*)&h0; u.y = *(uint32_t*)&h1;
    ((uint2*)(xr + (size_t)bt * E_))[c] = u;
}

// ---------------- bias pack ----------------
__global__ void pack_bias_kernel(const float* __restrict__ bq,
                                 const float* __restrict__ bk,
                                 const float* __restrict__ bv,
                                 float* __restrict__ o) {
    int l = blockIdx.y;
    int i = blockIdx.x * 256 + threadIdx.x;
    int w = i >> 10, c = i & 1023;
    const float* s = (w == 0) ? bq : (w == 1) ? bk : bv;
    o[l * E3 + i] = s[l * E_ + c];
}

// ---------------- weight transpose + fp16 round (vectorized, kept from R13) --------
__global__ void tconv_kernel(const float* __restrict__ W,
                             __half* __restrict__ To,
                             int K, int N, size_t lso) {
    __shared__ float tile[32][33];
    const float* Wl = W + (size_t)blockIdx.z * K * N;
    __half* Tol = To + (size_t)blockIdx.z * lso;
    int n0 = blockIdx.x * 32, k0 = blockIdx.y * 32;
    int tid = threadIdx.x;
    int row = tid >> 3;
    int c4  = (tid & 7) * 4;

    float4 v = *(const float4*)(Wl + (size_t)(k0 + row) * N + n0 + c4);
    tile[row][c4 + 0] = v.x; tile[row][c4 + 1] = v.y;
    tile[row][c4 + 2] = v.z; tile[row][c4 + 3] = v.w;
    __syncthreads();

    __half2 ha = __halves2half2(__float2half_rn(tile[c4 + 0][row]),
                                __float2half_rn(tile[c4 + 1][row]));
    __half2 hb = __halves2half2(__float2half_rn(tile[c4 + 2][row]),
                                __float2half_rn(tile[c4 + 3][row]));
    uint2 u; u.x = *(uint32_t*)&ha; u.y = *(uint32_t*)&hb;
    *(uint2*)(Tol + (size_t)(n0 + row) * K + k0 + c4) = u;
}

// ================= fp16 GEMM (R12 mainloop): 128x128 CTA, K-chunk 64, 3-stage, occ 2 =
// MODE: 0 = fp32 out, 2 = fp16 out.
#define STP 128
#define STT (128 * STP)
#define STB (2 * STT)
#define GSM (3 * STB)

template<int RELU, int MODE>
__global__ __launch_bounds__(256, 2)
void h16_gemm_kernel(const __half* __restrict__ A, const __half* __restrict__ Bt,
                     const float* __restrict__ bias,
                     float* __restrict__ Cf, __half* __restrict__ Ch,
                     int M, int N, int K) {
    extern __shared__ char smem_raw[];
    uint32_t sb = smem_u32(smem_raw);

    int tid = threadIdx.x, wid = tid >> 5, lane = tid & 31;
    int g = lane >> 2, tq = lane & 3;
    int wm = (wid >> 2) * 64;
    int wn = (wid & 3) * 32;
    int bm = blockIdx.y * 128, bn = blockIdx.x * 128;

    const __half* baseA = A  + (size_t)bm * K;
    const __half* baseB = Bt + (size_t)bn * K;
    int nch = K / 64;

    auto load_chunk = [&](int ci, int s) {
        uint32_t st = sb + s * STB;
        int k0 = ci * 64;
        #pragma unroll
        for (int j = 0; j < 8; j++) {
            int seg  = tid + j * 256;
            int tens = seg >> 10;
            int rem  = seg & 1023;
            int row  = rem >> 3;
            int c    = rem & 7;
            uint32_t dst = st + tens * STT + row * STP + ((c ^ (row & 7)) << 4);
            const __half* src = (tens ? baseB : baseA) + (size_t)row * K + k0 + c * 8;
            cpa16(dst, src);
        }
        asm volatile("cp.async.commit_group;" ::: "memory");
    };

    float acc[4][4][4];
    #pragma unroll
    for (int a = 0; a < 4; a++)
        #pragma unroll
        for (int b = 0; b < 4; b++)
            #pragma unroll
            for (int c = 0; c < 4; c++) acc[a][b][c] = 0.f;

    load_chunk(0, 0);
    load_chunk(1, 1);
    load_chunk(2, 2);

    int arow_l = lane & 15;
    int acb    = lane >> 4;
    int brow_l = (lane & 7) + ((lane >> 4) << 3);
    int bcb    = (lane >> 3) & 1;

    for (int i = 0; i < nch; i++) {
        int rem = nch - 1 - i;
        if (rem >= 2)      asm volatile("cp.async.wait_group 2;" ::: "memory");
        else if (rem == 1) asm volatile("cp.async.wait_group 1;" ::: "memory");
        else               asm volatile("cp.async.wait_group 0;" ::: "memory");
        __syncthreads();

        uint32_t stA = sb + (i % 3) * STB;
        uint32_t stB = stA + STT;

        #pragma unroll
        for (int kk = 0; kk < 4; kk++) {
            uint32_t af[4][4], bf[2][4];
            #pragma unroll
            for (int mi = 0; mi < 4; mi++) {
                int r = wm + mi * 16 + arow_l;
                int c = kk * 2 + acb;
                ldsm4(af[mi], stA + r * STP + ((c ^ (r & 7)) << 4));
            }
            #pragma unroll
            for (int nb = 0; nb < 2; nb++) {
                int r = wn + nb * 16 + brow_l;
                int c = kk * 2 + bcb;
                ldsm4(bf[nb], stB + r * STP + ((c ^ (r & 7)) << 4));
            }
            #pragma unroll
            for (int mi = 0; mi < 4; mi++)
                #pragma unroll
                for (int ni = 0; ni < 4; ni++) {
                    int nb = ni >> 1, o = (ni & 1) * 2;
                    mma_f16(acc[mi][ni], af[mi], bf[nb][o], bf[nb][o + 1]);
                }
        }
        __syncthreads();
        if (i + 3 < nch) load_chunk(i + 3, i % 3);
    }

    #pragma unroll
    for (int mi = 0; mi < 4; mi++) {
        int r0 = bm + wm + mi * 16 + g;
        #pragma unroll
        for (int ni = 0; ni < 4; ni++) {
            int c0 = bn + wn + ni * 8 + 2 * tq;
            float bx = bias[c0], by = bias[c0 + 1];
            float2 v0, v1;
            v0.x = acc[mi][ni][0] + bx; v0.y = acc[mi][ni][1] + by;
            v1.x = acc[mi][ni][2] + bx; v1.y = acc[mi][ni][3] + by;
            if (RELU) {
                v0.x = fmaxf(v0.x, 0.f); v0.y = fmaxf(v0.y, 0.f);
                v1.x = fmaxf(v1.x, 0.f); v1.y = fmaxf(v1.y, 0.f);
            }
            if (MODE == 0) {
                *(float2*)(Cf + (size_t)r0 * N + c0)       = v0;
                *(float2*)(Cf + (size_t)(r0 + 8) * N + c0) = v1;
            } else {
                __half2 h0 = __floats2half2_rn(v0.x, v0.y);
                __half2 h1 = __floats2half2_rn(v1.x, v1.y);
                *(__half2*)(Ch + (size_t)r0 * N + c0)       = h0;
                *(__half2*)(Ch + (size_t)(r0 + 8) * N + c0) = h1;
            }
        }
    }
}

// ================= fused flash attention (fp16 mma, double-buffered K/V) ============
// grid (16, B*H), block 128. smem: Q + 2xK + 2xV + P = 6 tiles.
#define FPH 72
#define FHB (FPH * 2)
#define HT_BYTES (64 * FHB)
#define FSMEM (6 * HT_BYTES)

__global__ __launch_bounds__(128)
void flash_kernel(const __half* __restrict__ qkv, __half* __restrict__ xr) {
    extern __shared__ __align__(16) char fsm[];
    uint32_t sbQ = smem_u32(fsm);
    uint32_t sbK0 = sbQ + HT_BYTES;          // stages: K0,K1,V0,V1
    uint32_t sbV0 = sbQ + 3 * HT_BYTES;
    uint32_t sbP  = sbQ + 5 * HT_BYTES;
    __half* Psp = (__half*)(fsm + 5 * HT_BYTES);

    int it = (int)gridDim.x - 1 - (int)blockIdx.x;
    int bh = blockIdx.y;
    int b = bh >> 4, h = bh & 15;
    int tid = threadIdx.x, wid = tid >> 5, lane = tid & 31;
    int g = lane >> 2, tq = lane & 3;
    int wm = wid * 16;

    int arow_l = lane & 15;
    int acb    = lane >> 4;
    int brow_l = (lane & 7) + ((lane >> 4) << 3);
    int bcb    = (lane >> 3) & 1;
    int jrow   = (lane & 7) + ((lane >> 3) & 1) * 8;
    int dcol   = (lane >> 4) * 8;

    const __half* kbase = qkv + (size_t)(b * T_) * E3 + E_     + h * HD;
    const __half* vbase = qkv + (size_t)(b * T_) * E3 + 2 * E_ + h * HD;

    auto load_kv = [&](int jt, int s) {
        const __half* kb = kbase + (size_t)jt * 64 * E3;
        const __half* vb = vbase + (size_t)jt * 64 * E3;
        uint32_t dK = sbK0 + s * HT_BYTES;
        uint32_t dV = sbV0 + s * HT_BYTES;
        #pragma unroll
        for (int p = 0; p < 4; p++) {
            int seg = tid + p * 128;
            int r = seg >> 3, c = seg & 7;
            cpa16(dK + (uint32_t)(r * FHB + c * 16), kb + (size_t)r * E3 + c * 8);
            cpa16(dV + (uint32_t)(r * FHB + c * 16), vb + (size_t)r * E3 + c * 8);
        }
        asm volatile("cp.async.commit_group;" ::: "memory");
    };

    // ---- load Q tile + first K/V ----
    const __half* qbase = qkv + (size_t)(b * T_ + it * 64) * E3 + h * HD;
    #pragma unroll
    for (int p = 0; p < 4; p++) {
        int seg = tid + p * 128;
        int r = seg >> 3, c = seg & 7;
        cpa16(sbQ + (uint32_t)(r * FHB + c * 16), qbase + (size_t)r * E3 + c * 8);
    }
    asm volatile("cp.async.commit_group;" ::: "memory");
    load_kv(0, 0);
    asm volatile("cp.async.wait_group 1;" ::: "memory");   // Q done
    __syncthreads();

    uint32_t qf[4][4];
    #pragma unroll
    for (int kk = 0; kk < 4; kk++)
        ldsm4(qf[kk], sbQ + (uint32_t)((wm + arow_l) * FHB + (kk * 16 + acb * 8) * 2));

    float m0 = -1e30f, m1 = -1e30f, l0 = 0.f, l1 = 0.f;
    float oac[8][4];
    #pragma unroll
    for (int n = 0; n < 8; n++)
        #pragma unroll
        for (int c = 0; c < 4; c++) oac[n][c] = 0.f;

    for (int jt = 0; jt <= it; jt++) {
        int cur = jt & 1;
        // prefetch next K/V into the idle stage (safe: end-of-iter barrier at jt-1
        // guaranteed all warps finished reading that stage)
        if (jt + 1 <= it) {
            load_kv(jt + 1, 1 - cur);
            asm volatile("cp.async.wait_group 1;" ::: "memory");   // stage cur ready
        } else {
            asm volatile("cp.async.wait_group 0;" ::: "memory");
        }
        __syncthreads();

        uint32_t sK = sbK0 + cur * HT_BYTES;
        uint32_t sV = sbV0 + cur * HT_BYTES;

        // ---- S = Q K^T ----
        float sac[8][4];
        #pragma unroll
        for (int n = 0; n < 8; n++)
            #pragma unroll
            for (int c = 0; c < 4; c++) sac[n][c] = 0.f;
        #pragma unroll
        for (int kk = 0; kk < 4; kk++) {
            uint32_t bfK[4][4];
            #pragma unroll
            for (int nb = 0; nb < 4; nb++)
                ldsm4(bfK[nb], sK + (uint32_t)((nb * 16 + brow_l) * FHB + (kk * 16 + bcb * 8) * 2));
            #pragma unroll
            for (int ni = 0; ni < 8; ni++) {
                int nb = ni >> 1, o = (ni & 1) * 2;
                mma_f16(sac[ni], qf[kk], bfK[nb][o], bfK[nb][o + 1]);
            }
        }

        // ---- online softmax ----
        #pragma unroll
        for (int ni = 0; ni < 8; ni++) {
            sac[ni][0] *= 0.125f; sac[ni][1] *= 0.125f;
            sac[ni][2] *= 0.125f; sac[ni][3] *= 0.125f;
        }
        if (jt == it) {
            #pragma unroll
            for (int ni = 0; ni < 8; ni++) {
                int cb = ni * 8 + 2 * tq;
                int r0 = wm + g, r1 = wm + g + 8;
                if (cb     > r0) sac[ni][0] = -1e30f;
                if (cb + 1 > r0) sac[ni][1] = -1e30f;
                if (cb     > r1) sac[ni][2] = -1e30f;
                if (cb + 1 > r1) sac[ni][3] = -1e30f;
            }
        }
        float a0 = -1e30f, a1 = -1e30f;
        #pragma unroll
        for (int ni = 0; ni < 8; ni++) {
            a0 = fmaxf(a0, fmaxf(sac[ni][0], sac[ni][1]));
            a1 = fmaxf(a1, fmaxf(sac[ni][2], sac[ni][3]));
        }
        a0 = fmaxf(a0, __shfl_xor_sync(0xffffffffu, a0, 1));
        a0 = fmaxf(a0, __shfl_xor_sync(0xffffffffu, a0, 2));
        a1 = fmaxf(a1, __shfl_xor_sync(0xffffffffu, a1, 1));
        a1 = fmaxf(a1, __shfl_xor_sync(0xffffffffu, a1, 2));
        float mn0 = fmaxf(m0, a0), mn1 = fmaxf(m1, a1);
        float al0 = __expf(m0 - mn0), al1 = __expf(m1 - mn1);
        m0 = mn0; m1 = mn1;
        l0 *= al0; l1 *= al1;
        #pragma unroll
        for (int ni = 0; ni < 8; ni++) {
            oac[ni][0] *= al0; oac[ni][1] *= al0;
            oac[ni][2] *= al1; oac[ni][3] *= al1;
        }
        float s0 = 0.f, s1 = 0.f;
        #pragma unroll
        for (int ni = 0; ni < 8; ni++) {
            __half2 hp0 = __floats2half2_rn(__expf(sac[ni][0] - mn0), __expf(sac[ni][1] - mn0));
            __half2 hp1 = __floats2half2_rn(__expf(sac[ni][2] - mn1), __expf(sac[ni][3] - mn1));
            s0 += __low2float(hp0) + __high2float(hp0);
            s1 += __low2float(hp1) + __high2float(hp1);
            int cb = ni * 8 + 2 * tq;
            *(__half2*)(Psp + (wm + g) * FPH + cb)     = hp0;
            *(__half2*)(Psp + (wm + g + 8) * FPH + cb) = hp1;
        }
        s0 += __shfl_xor_sync(0xffffffffu, s0, 1);
        s0 += __shfl_xor_sync(0xffffffffu, s0, 2);
        s1 += __shfl_xor_sync(0xffffffffu, s1, 1);
        s1 += __shfl_xor_sync(0xffffffffu, s1, 2);
        l0 += s0; l1 += s1;
        __syncwarp();

        // ---- O += P V ----
        #pragma unroll
        for (int jb = 0; jb < 4; jb++) {
            uint32_t pf[4];
            ldsm4(pf, sbP + (uint32_t)((wm + arow_l) * FHB + (jb * 16 + acb * 8) * 2));
            #pragma unroll
            for (int db = 0; db < 4; db++) {
                uint32_t vf[4];
                ldsm4t(vf, sV + (uint32_t)((jb * 16 + jrow) * FHB + (db * 16 + dcol) * 2));
                mma_f16(oac[db * 2],     pf, vf[0], vf[1]);
                mma_f16(oac[db * 2 + 1], pf, vf[2], vf[3]);
            }
        }
        __syncthreads();    // stage-reuse handshake (protects cur for reload at jt+2)
    }

    float inv0 = 1.f / l0, inv1 = 1.f / l1;
    __half* od = xr + (size_t)(b * T_ + it * 64 + wm + g) * E_ + h * HD;
    #pragma unroll
    for (int nd = 0; nd < 8; nd++) {
        int cb = nd * 8 + 2 * tq;
        __half2 v0 = __floats2half2_rn(oac[nd][0] * inv0, oac[nd][1] * inv0);
        __half2 v1 = __floats2half2_rn(oac[nd][2] * inv1, oac[nd][3] * inv1);
        *(__half2*)(od + cb)                  = v0;
        *(__half2*)(od + (size_t)8 * E_ + cb) = v1;
    }
}

// ---------------- out = LayerNorm(in (+ res)) ----------------
__global__ void add_ln_kernel(const float* __restrict__ in,
                              const float* __restrict__ res,
                              const float* __restrict__ g,
                              const float* __restrict__ bb,
                              float* __restrict__ out,
                              __half* __restrict__ outr) {
    int row = blockIdx.x;
    int t = threadIdx.x;
    float4 v = ((const float4*)(in + (size_t)row * E_))[t];
    if (res) {
        float4 r = ((const float4*)(res + (size_t)row * E_))[t];
        v.x += r.x; v.y += r.y; v.z += r.z; v.w += r.w;
    }
    float s  = v.x + v.y + v.z + v.w;
    float s2 = v.x * v.x + v.y * v.y + v.z * v.z + v.w * v.w;

    __shared__ float sh[16];
    s = warpSum(s); s2 = warpSum(s2);
    int w = t >> 5, lane = t & 31;
    if (lane == 0) { sh[w] = s; sh[w + 8] = s2; }
    __syncthreads();
    if (w == 0) {
        float a  = (lane < 8) ? sh[lane] : 0.f;
        a = warpSum(a);
        float a2 = (lane < 8) ? sh[lane + 8] : 0.f;
        a2 = warpSum(a2);
        if (lane == 0) { sh[0] = a; sh[8] = a2; }
    }
    __syncthreads();
    float mean = sh[0] * (1.f / E_);
    float var  = sh[8] * (1.f / E_) - mean * mean;
    float rstd = rsqrtf(var + 1e-5f);

    float4 gv = ((const float4*)g)[t];
    float4 bv = ((const float4*)bb)[t];
    float4 o;
    o.x = (v.x - mean) * rstd * gv.x + bv.x;
    o.y = (v.y - mean) * rstd * gv.y + bv.y;
    o.z = (v.z - mean) * rstd * gv.z + bv.z;
    o.w = (v.w - mean) * rstd * gv.w + bv.w;
    ((float4*)(out + (size_t)row * E_))[t] = o;

    __half2 h0 = __floats2half2_rn(o.x, o.y);
    __half2 h1 = __floats2half2_rn(o.z, o.w);
    uint2 u; u.x = *(uint32_t*)&h0; u.y = *(uint32_t*)&h1;
    ((uint2*)(outr + (size_t)row * E_))[t] = u;
}

// ---------------- host launch ----------------
extern "C" void kernel_launch(void* const* d_in, const int* in_sizes, int n_in,
                              void* d_out, int out_size) {
    const int*   idx   = (const int*)  d_in[0];
    const float* tok   = (const float*)d_in[1];
    const float* pos   = (const float*)d_in[2];
    const float* Wq    = (const float*)d_in[3];
    const float* bq    = (const float*)d_in[4];
    const float* Wk    = (const float*)d_in[5];
    const float* bk    = (const float*)d_in[6];
    const float* Wv    = (const float*)d_in[7];
    const float* bv    = (const float*)d_in[8];
    const float* Wo    = (const float*)d_in[9];
    const float* bo    = (const float*)d_in[10];
    const float* W1    = (const float*)d_in[11];
    const float* b1    = (const float*)d_in[12];
    const float* W2    = (const float*)d_in[13];
    const float* b2    = (const float*)d_in[14];
    const float* ln1g  = (const float*)d_in[15];
    const float* ln1b  = (const float*)d_in[16];
    const float* ln2g  = (const float*)d_in[17];
    const float* ln2b  = (const float*)d_in[18];
    const float* lnfg  = (const float*)d_in[19];
    const float* lnfb  = (const float*)d_in[20];
    const float* Whead = (const float*)d_in[21];
    const float* bhead = (const float*)d_in[22];
    float* out = (float*)d_out;

    float *x, *tmp, *bqkv;
    __half *xr, *qkvh, *ffr, *wt;
    cudaGetSymbolAddress((void**)&x,    g_x);
    cudaGetSymbolAddress((void**)&xr,   g_xr);
    cudaGetSymbolAddress((void**)&qkvh, g_qkvh);
    cudaGetSymbolAddress((void**)&tmp,  g_tmp);
    cudaGetSymbolAddress((void**)&ffr,  g_ffr);
    cudaGetSymbolAddress((void**)&bqkv, g_bqkv);
    cudaGetSymbolAddress((void**)&wt,   g_wt);

    cudaFuncSetAttribute(h16_gemm_kernel<0,0>,
                         cudaFuncAttributeMaxDynamicSharedMemorySize, GSM);
    cudaFuncSetAttribute(h16_gemm_kernel<0,2>,
                         cudaFuncAttributeMaxDynamicSharedMemorySize, GSM);
    cudaFuncSetAttribute(h16_gemm_kernel<1,2>,
                         cudaFuncAttributeMaxDynamicSharedMemorySize, GSM);
    cudaFuncSetAttribute(flash_kernel,
                         cudaFuncAttributeMaxDynamicSharedMemorySize, FSMEM);

    tconv_kernel<<<dim3(E_ / 32,  E_ / 32,  L_), 256>>>(Wq, wt + OQKV,             E_, E_, 3 * SZ_EE);
    tconv_kernel<<<dim3(E_ / 32,  E_ / 32,  L_), 256>>>(Wk, wt + OQKV + SZ_EE,     E_, E_, 3 * SZ_EE);
    tconv_kernel<<<dim3(E_ / 32,  E_ / 32,  L_), 256>>>(Wv, wt + OQKV + 2 * SZ_EE, E_, E_, 3 * SZ_EE);
    tconv_kernel<<<dim3(E_ / 32,  E_ / 32,  L_), 256>>>(Wo, wt + OWO,  E_,  E_,  SZ_EE);
    tconv_kernel<<<dim3(FF_ / 32, E_ / 32,  L_), 256>>>(W1, wt + OW1,  E_,  FF_, (size_t)E_ * FF_);
    tconv_kernel<<<dim3(E_ / 32,  FF_ / 32, L_), 256>>>(W2, wt + OW2,  FF_, E_,  (size_t)E_ * FF_);
    tconv_kernel<<<dim3(V_ / 32,  E_ / 32,  1 ), 256>>>(Whead, wt + OHEAD, E_, V_, 0);
    pack_bias_kernel<<<dim3(12, L_), 256>>>(bq, bk, bv, bqkv);

    embed_kernel<<<BT, 256>>>(idx, tok, pos, x, xr);

    dim3 gQKV(E3 / 128, BT / 128);
    dim3 gEE(E_ / 128, BT / 128);
    dim3 gEF(FF_ / 128, BT / 128);
    dim3 gHead(V_ / 128, BT / 128);

    for (int l = 0; l < L_; l++) {
        h16_gemm_kernel<0,2><<<gQKV, 256, GSM>>>(
            xr, wt + OQKV + (size_t)l * 3 * SZ_EE, bqkv + l * E3,
            nullptr, qkvh, BT, E3, E_);

        flash_kernel<<<dim3(16, B_ * H_), 128, FSMEM>>>(qkvh, xr);

        h16_gemm_kernel<0,0><<<gEE, 256, GSM>>>(
            xr, wt + OWO + (size_t)l * SZ_EE, bo + l * E_,
            tmp, nullptr, BT, E_, E_);
        add_ln_kernel<<<BT, 256>>>(x, tmp, ln1g + l * E_, ln1b + l * E_, x, xr);

        h16_gemm_kernel<1,2><<<gEF, 256, GSM>>>(
            xr, wt + OW1 + (size_t)l * E_ * FF_, b1 + l * FF_,
            nullptr, ffr, BT, FF_, E_);
        h16_gemm_kernel<0,0><<<gEE, 256, GSM>>>(
            ffr, wt + OW2 + (size_t)l * E_ * FF_, b2 + l * E_,
            tmp, nullptr, BT, E_, FF_);
        add_ln_kernel<<<BT, 256>>>(x, tmp, ln2g + l * E_, ln2b + l * E_, x, xr);
    }

    add_ln_kernel<<<BT, 256>>>(x, nullptr, lnfg, lnfb, x, xr);
    h16_gemm_kernel<0,0><<<gHead, 256, GSM>>>(
        xr, wt + OHEAD, bhead, out, nullptr, BT, V_, E_);
}

// round 15
// speedup vs baseline: 1.0487x; 1.0164x over previous
#include <cuda_runtime.h>
#include <cuda_fp16.h>
#include <math.h>
#include <stdint.h>

#define B_  4
#define T_  1024
#define E_  1024
#define H_  16
#define HD  64
#define L_  6
#define FF_ 4096
#define V_  32000
#define BT  (B_ * T_)
#define E3  (3 * E_)

#define SZ_EE ((size_t)E_ * E_)
#define OQKV  ((size_t)0)
#define OWO   ((size_t)18 * SZ_EE)
#define OW1   ((size_t)24 * SZ_EE)
#define OW2   ((size_t)48 * SZ_EE)
#define OHEAD ((size_t)72 * SZ_EE)
#define WTOT  (OHEAD + (size_t)E_ * V_)

// ---------------- device scratch ----------------
__device__ __half g_x[BT * E_];              // fp16 residual / LN-out / GEMM input
__device__ __half g_qkvh[(size_t)BT * E3];   // fp16 QKV (flash input)
__device__ __half g_tmp[BT * E_];            // fp16 GEMM output (pre-residual)
__device__ __half g_ffr[(size_t)BT * FF_];   // FF activations; front BT*E reused as attn-out
__device__ float  g_bqkv[L_ * E3];
__device__ __half g_wt[WTOT];

// ---------------- helpers ----------------
__device__ __forceinline__ uint32_t smem_u32(const void* p) {
    uint32_t a;
    asm("{ .reg .u64 t; cvta.to.shared.u64 t, %1; cvt.u32.u64 %0, t; }" : "=r"(a) : "l"(p));
    return a;
}
__device__ __forceinline__ float warpSum(float v) {
    #pragma unroll
    for (int o = 16; o > 0; o >>= 1) v += __shfl_xor_sync(0xffffffffu, v, o);
    return v;
}
__device__ __forceinline__ void ldsm4(uint32_t* r, uint32_t addr) {
    asm volatile("ldmatrix.sync.aligned.m8n8.x4.shared.b16 {%0,%1,%2,%3}, [%4];"
                 : "=r"(r[0]), "=r"(r[1]), "=r"(r[2]), "=r"(r[3]) : "r"(addr));
}
__device__ __forceinline__ void ldsm4t(uint32_t* r, uint32_t addr) {
    asm volatile("ldmatrix.sync.aligned.m8n8.x4.trans.shared.b16 {%0,%1,%2,%3}, [%4];"
                 : "=r"(r[0]), "=r"(r[1]), "=r"(r[2]), "=r"(r[3]) : "r"(addr));
}
__device__ __forceinline__ void cpa16(uint32_t dst, const void* src) {
    asm volatile("cp.async.cg.shared.global [%0], [%1], 16;" :: "r"(dst), "l"(src));
}
__device__ __forceinline__ void mma_f16(float* c, const uint32_t* a, uint32_t b0, uint32_t b1) {
    asm volatile(
        "mma.sync.aligned.m16n8k16.row.col.f32.f16.f16.f32 "
        "{%0,%1,%2,%3}, {%4,%5,%6,%7}, {%8,%9}, {%0,%1,%2,%3};\n"
        : "+f"(c[0]), "+f"(c[1]), "+f"(c[2]), "+f"(c[3])
        : "r"(a[0]), "r"(a[1]), "r"(a[2]), "r"(a[3]), "r"(b0), "r"(b1));
}

// ---------------- embedding (writes fp16 x directly) ----------------
__global__ void embed_kernel(const int* __restrict__ idx,
                             const float* __restrict__ tok,
                             const float* __restrict__ pos,
                             __half* __restrict__ x) {
    int bt = blockIdx.x;
    int t  = bt & (T_ - 1);
    int id = idx[bt];
    int c  = threadIdx.x;
    float4 a = ((const float4*)(tok + (size_t)id * E_))[c];
    float4 p = ((const float4*)(pos + (size_t)t  * E_))[c];
    a.x += p.x; a.y += p.y; a.z += p.z; a.w += p.w;
    __half2 h0 = __floats2half2_rn(a.x, a.y);
    __half2 h1 = __floats2half2_rn(a.z, a.w);
    uint2 u; u.x = *(uint32_t*)&h0; u.y = *(uint32_t*)&h1;
    ((uint2*)(x + (size_t)bt * E_))[c] = u;
}

// ---------------- bias pack ----------------
__global__ void pack_bias_kernel(const float* __restrict__ bq,
                                 const float* __restrict__ bk,
                                 const float* __restrict__ bv,
                                 float* __restrict__ o) {
    int l = blockIdx.y;
    int i = blockIdx.x * 256 + threadIdx.x;
    int w = i >> 10, c = i & 1023;
    const float* s = (w == 0) ? bq : (w == 1) ? bk : bv;
    o[l * E3 + i] = s[l * E_ + c];
}

// ---------------- weight transpose + fp16 round (vectorized) ----------------
__global__ void tconv_kernel(const float* __restrict__ W,
                             __half* __restrict__ To,
                             int K, int N, size_t lso) {
    __shared__ float tile[32][33];
    const float* Wl = W + (size_t)blockIdx.z * K * N;
    __half* Tol = To + (size_t)blockIdx.z * lso;
    int n0 = blockIdx.x * 32, k0 = blockIdx.y * 32;
    int tid = threadIdx.x;
    int row = tid >> 3;
    int c4  = (tid & 7) * 4;

    float4 v = *(const float4*)(Wl + (size_t)(k0 + row) * N + n0 + c4);
    tile[row][c4 + 0] = v.x; tile[row][c4 + 1] = v.y;
    tile[row][c4 + 2] = v.z; tile[row][c4 + 3] = v.w;
    __syncthreads();

    __half2 ha = __halves2half2(__float2half_rn(tile[c4 + 0][row]),
                                __float2half_rn(tile[c4 + 1][row]));
    __half2 hb = __halves2half2(__float2half_rn(tile[c4 + 2][row]),
                                __float2half_rn(tile[c4 + 3][row]));
    uint2 u; u.x = *(uint32_t*)&ha; u.y = *(uint32_t*)&hb;
    *(uint2*)(Tol + (size_t)(n0 + row) * K + k0 + c4) = u;
}

// ================= fp16 GEMM (R12/R14 mainloop): 128x128 CTA, K-chunk 64, 3-stage, occ 2
// MODE: 0 = fp32 out, 2 = fp16 out.
#define STP 128
#define STT (128 * STP)
#define STB (2 * STT)
#define GSM (3 * STB)

template<int RELU, int MODE>
__global__ __launch_bounds__(256, 2)
void h16_gemm_kernel(const __half* __restrict__ A, const __half* __restrict__ Bt,
                     const float* __restrict__ bias,
                     float* __restrict__ Cf, __half* __restrict__ Ch,
                     int M, int N, int K) {
    extern __shared__ char smem_raw[];
    uint32_t sb = smem_u32(smem_raw);

    int tid = threadIdx.x, wid = tid >> 5, lane = tid & 31;
    int g = lane >> 2, tq = lane & 3;
    int wm = (wid >> 2) * 64;
    int wn = (wid & 3) * 32;
    int bm = blockIdx.y * 128, bn = blockIdx.x * 128;

    const __half* baseA = A  + (size_t)bm * K;
    const __half* baseB = Bt + (size_t)bn * K;
    int nch = K / 64;

    auto load_chunk = [&](int ci, int s) {
        uint32_t st = sb + s * STB;
        int k0 = ci * 64;
        #pragma unroll
        for (int j = 0; j < 8; j++) {
            int seg  = tid + j * 256;
            int tens = seg >> 10;
            int rem  = seg & 1023;
            int row  = rem >> 3;
            int c    = rem & 7;
            uint32_t dst = st + tens * STT + row * STP + ((c ^ (row & 7)) << 4);
            const __half* src = (tens ? baseB : baseA) + (size_t)row * K + k0 + c * 8;
            cpa16(dst, src);
        }
        asm volatile("cp.async.commit_group;" ::: "memory");
    };

    float acc[4][4][4];
    #pragma unroll
    for (int a = 0; a < 4; a++)
        #pragma unroll
        for (int b = 0; b < 4; b++)
            #pragma unroll
            for (int c = 0; c < 4; c++) acc[a][b][c] = 0.f;

    load_chunk(0, 0);
    load_chunk(1, 1);
    load_chunk(2, 2);

    int arow_l = lane & 15;
    int acb    = lane >> 4;
    int brow_l = (lane & 7) + ((lane >> 4) << 3);
    int bcb    = (lane >> 3) & 1;

    for (int i = 0; i < nch; i++) {
        int rem = nch - 1 - i;
        if (rem >= 2)      asm volatile("cp.async.wait_group 2;" ::: "memory");
        else if (rem == 1) asm volatile("cp.async.wait_group 1;" ::: "memory");
        else               asm volatile("cp.async.wait_group 0;" ::: "memory");
        __syncthreads();

        uint32_t stA = sb + (i % 3) * STB;
        uint32_t stB = stA + STT;

        #pragma unroll
        for (int kk = 0; kk < 4; kk++) {
            uint32_t af[4][4], bf[2][4];
            #pragma unroll
            for (int mi = 0; mi < 4; mi++) {
                int r = wm + mi * 16 + arow_l;
                int c = kk * 2 + acb;
                ldsm4(af[mi], stA + r * STP + ((c ^ (r & 7)) << 4));
            }
            #pragma unroll
            for (int nb = 0; nb < 2; nb++) {
                int r = wn + nb * 16 + brow_l;
                int c = kk * 2 + bcb;
                ldsm4(bf[nb], stB + r * STP + ((c ^ (r & 7)) << 4));
            }
            #pragma unroll
            for (int mi = 0; mi < 4; mi++)
                #pragma unroll
                for (int ni = 0; ni < 4; ni++) {
                    int nb = ni >> 1, o = (ni & 1) * 2;
                    mma_f16(acc[mi][ni], af[mi], bf[nb][o], bf[nb][o + 1]);
                }
        }
        __syncthreads();
        if (i + 3 < nch) load_chunk(i + 3, i % 3);
    }

    #pragma unroll
    for (int mi = 0; mi < 4; mi++) {
        int r0 = bm + wm + mi * 16 + g;
        #pragma unroll
        for (int ni = 0; ni < 4; ni++) {
            int c0 = bn + wn + ni * 8 + 2 * tq;
            float bx = bias[c0], by = bias[c0 + 1];
            float2 v0, v1;
            v0.x = acc[mi][ni][0] + bx; v0.y = acc[mi][ni][1] + by;
            v1.x = acc[mi][ni][2] + bx; v1.y = acc[mi][ni][3] + by;
            if (RELU) {
                v0.x = fmaxf(v0.x, 0.f); v0.y = fmaxf(v0.y, 0.f);
                v1.x = fmaxf(v1.x, 0.f); v1.y = fmaxf(v1.y, 0.f);
            }
            if (MODE == 0) {
                *(float2*)(Cf + (size_t)r0 * N + c0)       = v0;
                *(float2*)(Cf + (size_t)(r0 + 8) * N + c0) = v1;
            } else {
                __half2 h0 = __floats2half2_rn(v0.x, v0.y);
                __half2 h1 = __floats2half2_rn(v1.x, v1.y);
                *(__half2*)(Ch + (size_t)r0 * N + c0)       = h0;
                *(__half2*)(Ch + (size_t)(r0 + 8) * N + c0) = h1;
            }
        }
    }
}

// ================= fused flash attention (fp16 mma, double-buffered K/V) ============
#define FPH 72
#define FHB (FPH * 2)
#define HT_BYTES (64 * FHB)
#define FSMEM (6 * HT_BYTES)

__global__ __launch_bounds__(128)
void flash_kernel(const __half* __restrict__ qkv, __half* __restrict__ ao) {
    extern __shared__ __align__(16) char fsm[];
    uint32_t sbQ = smem_u32(fsm);
    uint32_t sbK0 = sbQ + HT_BYTES;
    uint32_t sbV0 = sbQ + 3 * HT_BYTES;
    uint32_t sbP  = sbQ + 5 * HT_BYTES;
    __half* Psp = (__half*)(fsm + 5 * HT_BYTES);

    int it = (int)gridDim.x - 1 - (int)blockIdx.x;
    int bh = blockIdx.y;
    int b = bh >> 4, h = bh & 15;
    int tid = threadIdx.x, wid = tid >> 5, lane = tid & 31;
    int g = lane >> 2, tq = lane & 3;
    int wm = wid * 16;

    int arow_l = lane & 15;
    int acb    = lane >> 4;
    int brow_l = (lane & 7) + ((lane >> 4) << 3);
    int bcb    = (lane >> 3) & 1;
    int jrow   = (lane & 7) + ((lane >> 3) & 1) * 8;
    int dcol   = (lane >> 4) * 8;

    const __half* kbase = qkv + (size_t)(b * T_) * E3 + E_     + h * HD;
    const __half* vbase = qkv + (size_t)(b * T_) * E3 + 2 * E_ + h * HD;

    auto load_kv = [&](int jt, int s) {
        const __half* kb = kbase + (size_t)jt * 64 * E3;
        const __half* vb = vbase + (size_t)jt * 64 * E3;
        uint32_t dK = sbK0 + s * HT_BYTES;
        uint32_t dV = sbV0 + s * HT_BYTES;
        #pragma unroll
        for (int p = 0; p < 4; p++) {
            int seg = tid + p * 128;
            int r = seg >> 3, c = seg & 7;
            cpa16(dK + (uint32_t)(r * FHB + c * 16), kb + (size_t)r * E3 + c * 8);
            cpa16(dV + (uint32_t)(r * FHB + c * 16), vb + (size_t)r * E3 + c * 8);
        }
        asm volatile("cp.async.commit_group;" ::: "memory");
    };

    const __half* qbase = qkv + (size_t)(b * T_ + it * 64) * E3 + h * HD;
    #pragma unroll
    for (int p = 0; p < 4; p++) {
        int seg = tid + p * 128;
        int r = seg >> 3, c = seg & 7;
        cpa16(sbQ + (uint32_t)(r * FHB + c * 16), qbase + (size_t)r * E3 + c * 8);
    }
    asm volatile("cp.async.commit_group;" ::: "memory");
    load_kv(0, 0);
    asm volatile("cp.async.wait_group 1;" ::: "memory");
    __syncthreads();

    uint32_t qf[4][4];
    #pragma unroll
    for (int kk = 0; kk < 4; kk++)
        ldsm4(qf[kk], sbQ + (uint32_t)((wm + arow_l) * FHB + (kk * 16 + acb * 8) * 2));

    float m0 = -1e30f, m1 = -1e30f, l0 = 0.f, l1 = 0.f;
    float oac[8][4];
    #pragma unroll
    for (int n = 0; n < 8; n++)
        #pragma unroll
        for (int c = 0; c < 4; c++) oac[n][c] = 0.f;

    for (int jt = 0; jt <= it; jt++) {
        int cur = jt & 1;
        if (jt + 1 <= it) {
            load_kv(jt + 1, 1 - cur);
            asm volatile("cp.async.wait_group 1;" ::: "memory");
        } else {
            asm volatile("cp.async.wait_group 0;" ::: "memory");
        }
        __syncthreads();

        uint32_t sK = sbK0 + cur * HT_BYTES;
        uint32_t sV = sbV0 + cur * HT_BYTES;

        float sac[8][4];
        #pragma unroll
        for (int n = 0; n < 8; n++)
            #pragma unroll
            for (int c = 0; c < 4; c++) sac[n][c] = 0.f;
        #pragma unroll
        for (int kk = 0; kk < 4; kk++) {
            uint32_t bfK[4][4];
            #pragma unroll
            for (int nb = 0; nb < 4; nb++)
                ldsm4(bfK[nb], sK + (uint32_t)((nb * 16 + brow_l) * FHB + (kk * 16 + bcb * 8) * 2));
            #pragma unroll
            for (int ni = 0; ni < 8; ni++) {
                int nb = ni >> 1, o = (ni & 1) * 2;
                mma_f16(sac[ni], qf[kk], bfK[nb][o], bfK[nb][o + 1]);
            }
        }

        #pragma unroll
        for (int ni = 0; ni < 8; ni++) {
            sac[ni][0] *= 0.125f; sac[ni][1] *= 0.125f;
            sac[ni][2] *= 0.125f; sac[ni][3] *= 0.125f;
        }
        if (jt == it) {
            #pragma unroll
            for (int ni = 0; ni < 8; ni++) {
                int cb = ni * 8 + 2 * tq;
                int r0 = wm + g, r1 = wm + g + 8;
                if (cb     > r0) sac[ni][0] = -1e30f;
                if (cb + 1 > r0) sac[ni][1] = -1e30f;
                if (cb     > r1) sac[ni][2] = -1e30f;
                if (cb + 1 > r1) sac[ni][3] = -1e30f;
            }
        }
        float a0 = -1e30f, a1 = -1e30f;
        #pragma unroll
        for (int ni = 0; ni < 8; ni++) {
            a0 = fmaxf(a0, fmaxf(sac[ni][0], sac[ni][1]));
            a1 = fmaxf(a1, fmaxf(sac[ni][2], sac[ni][3]));
        }
        a0 = fmaxf(a0, __shfl_xor_sync(0xffffffffu, a0, 1));
        a0 = fmaxf(a0, __shfl_xor_sync(0xffffffffu, a0, 2));
        a1 = fmaxf(a1, __shfl_xor_sync(0xffffffffu, a1, 1));
        a1 = fmaxf(a1, __shfl_xor_sync(0xffffffffu, a1, 2));
        float mn0 = fmaxf(m0, a0), mn1 = fmaxf(m1, a1);
        float al0 = __expf(m0 - mn0), al1 = __expf(m1 - mn1);
        m0 = mn0; m1 = mn1;
        l0 *= al0; l1 *= al1;
        #pragma unroll
        for (int ni = 0; ni < 8; ni++) {
            oac[ni][0] *= al0; oac[ni][1] *= al0;
            oac[ni][2] *= al1; oac[ni][3] *= al1;
        }
        float s0 = 0.f, s1 = 0.f;
        #pragma unroll
        for (int ni = 0; ni < 8; ni++) {
            __half2 hp0 = __floats2half2_rn(__expf(sac[ni][0] - mn0), __expf(sac[ni][1] - mn0));
            __half2 hp1 = __floats2half2_rn(__expf(sac[ni][2] - mn1), __expf(sac[ni][3] - mn1));
            s0 += __low2float(hp0) + __high2float(hp0);
            s1 += __low2float(hp1) + __high2float(hp1);
            int cb = ni * 8 + 2 * tq;
            *(__half2*)(Psp + (wm + g) * FPH + cb)     = hp0;
            *(__half2*)(Psp + (wm + g + 8) * FPH + cb) = hp1;
        }
        s0 += __shfl_xor_sync(0xffffffffu, s0, 1);
        s0 += __shfl_xor_sync(0xffffffffu, s0, 2);
        s1 += __shfl_xor_sync(0xffffffffu, s1, 1);
        s1 += __shfl_xor_sync(0xffffffffu, s1, 2);
        l0 += s0; l1 += s1;
        __syncwarp();

        #pragma unroll
        for (int jb = 0; jb < 4; jb++) {
            uint32_t pf[4];
            ldsm4(pf, sbP + (uint32_t)((wm + arow_l) * FHB + (jb * 16 + acb * 8) * 2));
            #pragma unroll
            for (int db = 0; db < 4; db++) {
                uint32_t vf[4];
                ldsm4t(vf, sV + (uint32_t)((jb * 16 + jrow) * FHB + (db * 16 + dcol) * 2));
                mma_f16(oac[db * 2],     pf, vf[0], vf[1]);
                mma_f16(oac[db * 2 + 1], pf, vf[2], vf[3]);
            }
        }
        __syncthreads();
    }

    float inv0 = 1.f / l0, inv1 = 1.f / l1;
    __half* od = ao + (size_t)(b * T_ + it * 64 + wm + g) * E_ + h * HD;
    #pragma unroll
    for (int nd = 0; nd < 8; nd++) {
        int cb = nd * 8 + 2 * tq;
        __half2 v0 = __floats2half2_rn(oac[nd][0] * inv0, oac[nd][1] * inv0);
        __half2 v1 = __floats2half2_rn(oac[nd][2] * inv1, oac[nd][3] * inv1);
        *(__half2*)(od + cb)                  = v0;
        *(__half2*)(od + (size_t)8 * E_ + cb) = v1;
    }
}

// ---------------- x = LayerNorm(in (+ res)) * g + b, all fp16 IO ----------------
__global__ void add_ln_kernel(const __half* __restrict__ in,
                              const __half* __restrict__ res,
                              const float* __restrict__ g,
                              const float* __restrict__ bb,
                              __half* __restrict__ out) {
    int row = blockIdx.x;
    int t = threadIdx.x;                 // 256 threads * 4 halves
    uint2 ui = ((const uint2*)(in + (size_t)row * E_))[t];
    __half2 i0 = *(__half2*)&ui.x, i1 = *(__half2*)&ui.y;
    float4 v;
    v.x = __low2float(i0); v.y = __high2float(i0);
    v.z = __low2float(i1); v.w = __high2float(i1);
    if (res) {
        uint2 ur = ((const uint2*)(res + (size_t)row * E_))[t];
        __half2 r0 = *(__half2*)&ur.x, r1 = *(__half2*)&ur.y;
        v.x += __low2float(r0); v.y += __high2float(r0);
        v.z += __low2float(r1); v.w += __high2float(r1);
    }
    float s  = v.x + v.y + v.z + v.w;
    float s2 = v.x * v.x + v.y * v.y + v.z * v.z + v.w * v.w;

    __shared__ float sh[16];
    s = warpSum(s); s2 = warpSum(s2);
    int w = t >> 5, lane = t & 31;
    if (lane == 0) { sh[w] = s; sh[w + 8] = s2; }
    __syncthreads();
    if (w == 0) {
        float a  = (lane < 8) ? sh[lane] : 0.f;
        a = warpSum(a);
        float a2 = (lane < 8) ? sh[lane + 8] : 0.f;
        a2 = warpSum(a2);
        if (lane == 0) { sh[0] = a; sh[8] = a2; }
    }
    __syncthreads();
    float mean = sh[0] * (1.f / E_);
    float var  = sh[8] * (1.f / E_) - mean * mean;
    float rstd = rsqrtf(var + 1e-5f);

    float4 gv = ((const float4*)g)[t];
    float4 bv = ((const float4*)bb)[t];
    float4 o;
    o.x = (v.x - mean) * rstd * gv.x + bv.x;
    o.y = (v.y - mean) * rstd * gv.y + bv.y;
    o.z = (v.z - mean) * rstd * gv.z + bv.z;
    o.w = (v.w - mean) * rstd * gv.w + bv.w;

    __half2 h0 = __floats2half2_rn(o.x, o.y);
    __half2 h1 = __floats2half2_rn(o.z, o.w);
    uint2 u; u.x = *(uint32_t*)&h0; u.y = *(uint32_t*)&h1;
    ((uint2*)(out + (size_t)row * E_))[t] = u;
}

// ---------------- host launch ----------------
extern "C" void kernel_launch(void* const* d_in, const int* in_sizes, int n_in,
                              void* d_out, int out_size) {
    const int*   idx   = (const int*)  d_in[0];
    const float* tok   = (const float*)d_in[1];
    const float* pos   = (const float*)d_in[2];
    const float* Wq    = (const float*)d_in[3];
    const float* bq    = (const float*)d_in[4];
    const float* Wk    = (const float*)d_in[5];
    const float* bk    = (const float*)d_in[6];
    const float* Wv    = (const float*)d_in[7];
    const float* bv    = (const float*)d_in[8];
    const float* Wo    = (const float*)d_in[9];
    const float* bo    = (const float*)d_in[10];
    const float* W1    = (const float*)d_in[11];
    const float* b1    = (const float*)d_in[12];
    const float* W2    = (const float*)d_in[13];
    const float* b2    = (const float*)d_in[14];
    const float* ln1g  = (const float*)d_in[15];
    const float* ln1b  = (const float*)d_in[16];
    const float* ln2g  = (const float*)d_in[17];
    const float* ln2b  = (const float*)d_in[18];
    const float* lnfg  = (const float*)d_in[19];
    const float* lnfb  = (const float*)d_in[20];
    const float* Whead = (const float*)d_in[21];
    const float* bhead = (const float*)d_in[22];
    float* out = (float*)d_out;

    float *bqkv;
    __half *x, *qkvh, *tmp, *ffr, *wt;
    cudaGetSymbolAddress((void**)&x,    g_x);
    cudaGetSymbolAddress((void**)&qkvh, g_qkvh);
    cudaGetSymbolAddress((void**)&tmp,  g_tmp);
    cudaGetSymbolAddress((void**)&ffr,  g_ffr);
    cudaGetSymbolAddress((void**)&bqkv, g_bqkv);
    cudaGetSymbolAddress((void**)&wt,   g_wt);

    __half* ao = ffr;    // attn-out scratch (front BT*E of ffr; consumed before FF1 writes)

    cudaFuncSetAttribute(h16_gemm_kernel<0,0>,
                         cudaFuncAttributeMaxDynamicSharedMemorySize, GSM);
    cudaFuncSetAttribute(h16_gemm_kernel<0,2>,
                         cudaFuncAttributeMaxDynamicSharedMemorySize, GSM);
    cudaFuncSetAttribute(h16_gemm_kernel<1,2>,
                         cudaFuncAttributeMaxDynamicSharedMemorySize, GSM);
    cudaFuncSetAttribute(flash_kernel,
                         cudaFuncAttributeMaxDynamicSharedMemorySize, FSMEM);

    tconv_kernel<<<dim3(E_ / 32,  E_ / 32,  L_), 256>>>(Wq, wt + OQKV,             E_, E_, 3 * SZ_EE);
    tconv_kernel<<<dim3(E_ / 32,  E_ / 32,  L_), 256>>>(Wk, wt + OQKV + SZ_EE,     E_, E_, 3 * SZ_EE);
    tconv_kernel<<<dim3(E_ / 32,  E_ / 32,  L_), 256>>>(Wv, wt + OQKV + 2 * SZ_EE, E_, E_, 3 * SZ_EE);
    tconv_kernel<<<dim3(E_ / 32,  E_ / 32,  L_), 256>>>(Wo, wt + OWO,  E_,  E_,  SZ_EE);
    tconv_kernel<<<dim3(FF_ / 32, E_ / 32,  L_), 256>>>(W1, wt + OW1,  E_,  FF_, (size_t)E_ * FF_);
    tconv_kernel<<<dim3(E_ / 32,  FF_ / 32, L_), 256>>>(W2, wt + OW2,  FF_, E_,  (size_t)E_ * FF_);
    tconv_kernel<<<dim3(V_ / 32,  E_ / 32,  1 ), 256>>>(Whead, wt + OHEAD, E_, V_, 0);
    pack_bias_kernel<<<dim3(12, L_), 256>>>(bq, bk, bv, bqkv);

    embed_kernel<<<BT, 256>>>(idx, tok, pos, x);

    dim3 gQKV(E3 / 128, BT / 128);
    dim3 gEE(E_ / 128, BT / 128);
    dim3 gEF(FF_ / 128, BT / 128);
    dim3 gHead(V_ / 128, BT / 128);

    for (int l = 0; l < L_; l++) {
        h16_gemm_kernel<0,2><<<gQKV, 256, GSM>>>(
            x, wt + OQKV + (size_t)l * 3 * SZ_EE, bqkv + l * E3,
            nullptr, qkvh, BT, E3, E_);

        flash_kernel<<<dim3(16, B_ * H_), 128, FSMEM>>>(qkvh, ao);

        h16_gemm_kernel<0,2><<<gEE, 256, GSM>>>(
            ao, wt + OWO + (size_t)l * SZ_EE, bo + l * E_,
            nullptr, tmp, BT, E_, E_);
        add_ln_kernel<<<BT, 256>>>(tmp, x, ln1g + l * E_, ln1b + l * E_, x);

        h16_gemm_kernel<1,2><<<gEF, 256, GSM>>>(
            x, wt + OW1 + (size_t)l * E_ * FF_, b1 + l * FF_,
            nullptr, ffr, BT, FF_, E_);
        h16_gemm_kernel<0,2><<<gEE, 256, GSM>>>(
            ffr, wt + OW2 + (size_t)l * E_ * FF_, b2 + l * E_,
            nullptr, tmp, BT, E_, FF_);
        add_ln_kernel<<<BT, 256>>>(tmp, x, ln2g + l * E_, ln2b + l * E_, x);
    }

    add_ln_kernel<<<BT, 256>>>(x, nullptr, lnfg, lnfb, x);
    h16_gemm_kernel<0,0><<<gHead, 256, GSM>>>(
        x, wt + OHEAD, bhead, out, nullptr, BT, V_, E_);
}

// round 16
// speedup vs baseline: 1.0581x; 1.0090x over previous
#include <cuda_runtime.h>
#include <cuda_fp16.h>
#include <math.h>
#include <stdint.h>

#define B_  4
#define T_  1024
#define E_  1024
#define H_  16
#define HD  64
#define L_  6
#define FF_ 4096
#define V_  32000
#define BT  (B_ * T_)
#define E3  (3 * E_)

#define SZ_EE ((size_t)E_ * E_)
#define OQKV  ((size_t)0)
#define OWO   ((size_t)18 * SZ_EE)
#define OW1   ((size_t)24 * SZ_EE)
#define OW2   ((size_t)48 * SZ_EE)
#define OHEAD ((size_t)72 * SZ_EE)
#define WTOT  (OHEAD + (size_t)E_ * V_)

// ---------------- device scratch ----------------
__device__ __half g_x[BT * E_];              // fp16 residual / LN-out / GEMM input
__device__ __half g_qkvh[(size_t)BT * E3];   // fp16 QKV (flash input)
__device__ __half g_tmp[BT * E_];            // fp16 GEMM output (pre-residual)
__device__ __half g_ffr[(size_t)BT * FF_];   // FF activations; front BT*E reused as attn-out
__device__ float  g_bqkv[L_ * E3];
__device__ __half g_wt[WTOT];

// ---------------- helpers ----------------
__device__ __forceinline__ uint32_t smem_u32(const void* p) {
    uint32_t a;
    asm("{ .reg .u64 t; cvta.to.shared.u64 t, %1; cvt.u32.u64 %0, t; }" : "=r"(a) : "l"(p));
    return a;
}
__device__ __forceinline__ float warpSum(float v) {
    #pragma unroll
    for (int o = 16; o > 0; o >>= 1) v += __shfl_xor_sync(0xffffffffu, v, o);
    return v;
}
__device__ __forceinline__ void ldsm4(uint32_t* r, uint32_t addr) {
    asm volatile("ldmatrix.sync.aligned.m8n8.x4.shared.b16 {%0,%1,%2,%3}, [%4];"
                 : "=r"(r[0]), "=r"(r[1]), "=r"(r[2]), "=r"(r[3]) : "r"(addr));
}
__device__ __forceinline__ void ldsm4t(uint32_t* r, uint32_t addr) {
    asm volatile("ldmatrix.sync.aligned.m8n8.x4.trans.shared.b16 {%0,%1,%2,%3}, [%4];"
                 : "=r"(r[0]), "=r"(r[1]), "=r"(r[2]), "=r"(r[3]) : "r"(addr));
}
__device__ __forceinline__ void cpa16(uint32_t dst, const void* src) {
    asm volatile("cp.async.cg.shared.global [%0], [%1], 16;" :: "r"(dst), "l"(src));
}
__device__ __forceinline__ void mma_f16(float* c, const uint32_t* a, uint32_t b0, uint32_t b1) {
    asm volatile(
        "mma.sync.aligned.m16n8k16.row.col.f32.f16.f16.f32 "
        "{%0,%1,%2,%3}, {%4,%5,%6,%7}, {%8,%9}, {%0,%1,%2,%3};\n"
        : "+f"(c[0]), "+f"(c[1]), "+f"(c[2]), "+f"(c[3])
        : "r"(a[0]), "r"(a[1]), "r"(a[2]), "r"(a[3]), "r"(b0), "r"(b1));
}

// ---------------- embedding (writes fp16 x directly) ----------------
__global__ void embed_kernel(const int* __restrict__ idx,
                             const float* __restrict__ tok,
                             const float* __restrict__ pos,
                             __half* __restrict__ x) {
    int bt = blockIdx.x;
    int t  = bt & (T_ - 1);
    int id = idx[bt];
    int c  = threadIdx.x;
    float4 a = ((const float4*)(tok + (size_t)id * E_))[c];
    float4 p = ((const float4*)(pos + (size_t)t  * E_))[c];
    a.x += p.x; a.y += p.y; a.z += p.z; a.w += p.w;
    __half2 h0 = __floats2half2_rn(a.x, a.y);
    __half2 h1 = __floats2half2_rn(a.z, a.w);
    uint2 u; u.x = *(uint32_t*)&h0; u.y = *(uint32_t*)&h1;
    ((uint2*)(x + (size_t)bt * E_))[c] = u;
}

// ---------------- bias pack ----------------
__global__ void pack_bias_kernel(const float* __restrict__ bq,
                                 const float* __restrict__ bk,
                                 const float* __restrict__ bv,
                                 float* __restrict__ o) {
    int l = blockIdx.y;
    int i = blockIdx.x * 256 + threadIdx.x;
    int w = i >> 10, c = i & 1023;
    const float* s = (w == 0) ? bq : (w == 1) ? bk : bv;
    o[l * E3 + i] = s[l * E_ + c];
}

// ---------------- weight transpose + fp16 round (4x ILP) ----------------
// Block: 128(k) x 32(n) input region = 4 sub-tiles of 32x32. 256 threads.
__global__ void tconv_kernel(const float* __restrict__ W,
                             __half* __restrict__ To,
                             int K, int N, size_t lso) {
    __shared__ float tile[4][32][33];
    const float* Wl = W + (size_t)blockIdx.z * K * N;
    __half* Tol = To + (size_t)blockIdx.z * lso;
    int n0 = blockIdx.x * 32, k0 = blockIdx.y * 128;
    int tid = threadIdx.x;
    int row = tid >> 3;             // 0..31
    int c4  = (tid & 7) * 4;        // 0,4,...,28

    float4 v[4];
    #pragma unroll
    for (int s = 0; s < 4; s++)
        v[s] = *(const float4*)(Wl + (size_t)(k0 + s * 32 + row) * N + n0 + c4);
    #pragma unroll
    for (int s = 0; s < 4; s++) {
        tile[s][row][c4 + 0] = v[s].x; tile[s][row][c4 + 1] = v[s].y;
        tile[s][row][c4 + 2] = v[s].z; tile[s][row][c4 + 3] = v[s].w;
    }
    __syncthreads();

    #pragma unroll
    for (int s = 0; s < 4; s++) {
        __half2 ha = __halves2half2(__float2half_rn(tile[s][c4 + 0][row]),
                                    __float2half_rn(tile[s][c4 + 1][row]));
        __half2 hb = __halves2half2(__float2half_rn(tile[s][c4 + 2][row]),
                                    __float2half_rn(tile[s][c4 + 3][row]));
        uint2 u; u.x = *(uint32_t*)&ha; u.y = *(uint32_t*)&hb;
        *(uint2*)(Tol + (size_t)(n0 + row) * K + k0 + s * 32 + c4) = u;
    }
}

// ================= fp16 GEMM (R12/R14 mainloop): 128x128 CTA, K-chunk 64, 3-stage, occ 2
// MODE: 0 = fp32 out, 2 = fp16 out.
#define STP 128
#define STT (128 * STP)
#define STB (2 * STT)
#define GSM (3 * STB)

template<int RELU, int MODE>
__global__ __launch_bounds__(256, 2)
void h16_gemm_kernel(const __half* __restrict__ A, const __half* __restrict__ Bt,
                     const float* __restrict__ bias,
                     float* __restrict__ Cf, __half* __restrict__ Ch,
                     int M, int N, int K) {
    extern __shared__ char smem_raw[];
    uint32_t sb = smem_u32(smem_raw);

    int tid = threadIdx.x, wid = tid >> 5, lane = tid & 31;
    int g = lane >> 2, tq = lane & 3;
    int wm = (wid >> 2) * 64;
    int wn = (wid & 3) * 32;
    int bm = blockIdx.y * 128, bn = blockIdx.x * 128;

    const __half* baseA = A  + (size_t)bm * K;
    const __half* baseB = Bt + (size_t)bn * K;
    int nch = K / 64;

    auto load_chunk = [&](int ci, int s) {
        uint32_t st = sb + s * STB;
        int k0 = ci * 64;
        #pragma unroll
        for (int j = 0; j < 8; j++) {
            int seg  = tid + j * 256;
            int tens = seg >> 10;
            int rem  = seg & 1023;
            int row  = rem >> 3;
            int c    = rem & 7;
            uint32_t dst = st + tens * STT + row * STP + ((c ^ (row & 7)) << 4);
            const __half* src = (tens ? baseB : baseA) + (size_t)row * K + k0 + c * 8;
            cpa16(dst, src);
        }
        asm volatile("cp.async.commit_group;" ::: "memory");
    };

    float acc[4][4][4];
    #pragma unroll
    for (int a = 0; a < 4; a++)
        #pragma unroll
        for (int b = 0; b < 4; b++)
            #pragma unroll
            for (int c = 0; c < 4; c++) acc[a][b][c] = 0.f;

    load_chunk(0, 0);
    load_chunk(1, 1);
    load_chunk(2, 2);

    int arow_l = lane & 15;
    int acb    = lane >> 4;
    int brow_l = (lane & 7) + ((lane >> 4) << 3);
    int bcb    = (lane >> 3) & 1;

    for (int i = 0; i < nch; i++) {
        int rem = nch - 1 - i;
        if (rem >= 2)      asm volatile("cp.async.wait_group 2;" ::: "memory");
        else if (rem == 1) asm volatile("cp.async.wait_group 1;" ::: "memory");
        else               asm volatile("cp.async.wait_group 0;" ::: "memory");
        __syncthreads();

        uint32_t stA = sb + (i % 3) * STB;
        uint32_t stB = stA + STT;

        #pragma unroll
        for (int kk = 0; kk < 4; kk++) {
            uint32_t af[4][4], bf[2][4];
            #pragma unroll
            for (int mi = 0; mi < 4; mi++) {
                int r = wm + mi * 16 + arow_l;
                int c = kk * 2 + acb;
                ldsm4(af[mi], stA + r * STP + ((c ^ (r & 7)) << 4));
            }
            #pragma unroll
            for (int nb = 0; nb < 2; nb++) {
                int r = wn + nb * 16 + brow_l;
                int c = kk * 2 + bcb;
                ldsm4(bf[nb], stB + r * STP + ((c ^ (r & 7)) << 4));
            }
            #pragma unroll
            for (int mi = 0; mi < 4; mi++)
                #pragma unroll
                for (int ni = 0; ni < 4; ni++) {
                    int nb = ni >> 1, o = (ni & 1) * 2;
                    mma_f16(acc[mi][ni], af[mi], bf[nb][o], bf[nb][o + 1]);
                }
        }
        __syncthreads();
        if (i + 3 < nch) load_chunk(i + 3, i % 3);
    }

    #pragma unroll
    for (int mi = 0; mi < 4; mi++) {
        int r0 = bm + wm + mi * 16 + g;
        #pragma unroll
        for (int ni = 0; ni < 4; ni++) {
            int c0 = bn + wn + ni * 8 + 2 * tq;
            float bx = bias[c0], by = bias[c0 + 1];
            float2 v0, v1;
            v0.x = acc[mi][ni][0] + bx; v0.y = acc[mi][ni][1] + by;
            v1.x = acc[mi][ni][2] + bx; v1.y = acc[mi][ni][3] + by;
            if (RELU) {
                v0.x = fmaxf(v0.x, 0.f); v0.y = fmaxf(v0.y, 0.f);
                v1.x = fmaxf(v1.x, 0.f); v1.y = fmaxf(v1.y, 0.f);
            }
            if (MODE == 0) {
                *(float2*)(Cf + (size_t)r0 * N + c0)       = v0;
                *(float2*)(Cf + (size_t)(r0 + 8) * N + c0) = v1;
            } else {
                __half2 h0 = __floats2half2_rn(v0.x, v0.y);
                __half2 h1 = __floats2half2_rn(v1.x, v1.y);
                *(__half2*)(Ch + (size_t)r0 * N + c0)       = h0;
                *(__half2*)(Ch + (size_t)(r0 + 8) * N + c0) = h1;
            }
        }
    }
}

// ================= fused flash attention (fp16 mma, double-buffered K/V) ============
#define FPH 72
#define FHB (FPH * 2)
#define HT_BYTES (64 * FHB)
#define FSMEM (6 * HT_BYTES)

__global__ __launch_bounds__(128)
void flash_kernel(const __half* __restrict__ qkv, __half* __restrict__ ao) {
    extern __shared__ __align__(16) char fsm[];
    uint32_t sbQ = smem_u32(fsm);
    uint32_t sbK0 = sbQ + HT_BYTES;
    uint32_t sbV0 = sbQ + 3 * HT_BYTES;
    uint32_t sbP  = sbQ + 5 * HT_BYTES;
    __half* Psp = (__half*)(fsm + 5 * HT_BYTES);

    int it = (int)gridDim.x - 1 - (int)blockIdx.x;
    int bh = blockIdx.y;
    int b = bh >> 4, h = bh & 15;
    int tid = threadIdx.x, wid = tid >> 5, lane = tid & 31;
    int g = lane >> 2, tq = lane & 3;
    int wm = wid * 16;

    int arow_l = lane & 15;
    int acb    = lane >> 4;
    int brow_l = (lane & 7) + ((lane >> 4) << 3);
    int bcb    = (lane >> 3) & 1;
    int jrow   = (lane & 7) + ((lane >> 3) & 1) * 8;
    int dcol   = (lane >> 4) * 8;

    const __half* kbase = qkv + (size_t)(b * T_) * E3 + E_     + h * HD;
    const __half* vbase = qkv + (size_t)(b * T_) * E3 + 2 * E_ + h * HD;

    auto load_kv = [&](int jt, int s) {
        const __half* kb = kbase + (size_t)jt * 64 * E3;
        const __half* vb = vbase + (size_t)jt * 64 * E3;
        uint32_t dK = sbK0 + s * HT_BYTES;
        uint32_t dV = sbV0 + s * HT_BYTES;
        #pragma unroll
        for (int p = 0; p < 4; p++) {
            int seg = tid + p * 128;
            int r = seg >> 3, c = seg & 7;
            cpa16(dK + (uint32_t)(r * FHB + c * 16), kb + (size_t)r * E3 + c * 8);
            cpa16(dV + (uint32_t)(r * FHB + c * 16), vb + (size_t)r * E3 + c * 8);
        }
        asm volatile("cp.async.commit_group;" ::: "memory");
    };

    const __half* qbase = qkv + (size_t)(b * T_ + it * 64) * E3 + h * HD;
    #pragma unroll
    for (int p = 0; p < 4; p++) {
        int seg = tid + p * 128;
        int r = seg >> 3, c = seg & 7;
        cpa16(sbQ + (uint32_t)(r * FHB + c * 16), qbase + (size_t)r * E3 + c * 8);
    }
    asm volatile("cp.async.commit_group;" ::: "memory");
    load_kv(0, 0);
    asm volatile("cp.async.wait_group 1;" ::: "memory");
    __syncthreads();

    uint32_t qf[4][4];
    #pragma unroll
    for (int kk = 0; kk < 4; kk++)
        ldsm4(qf[kk], sbQ + (uint32_t)((wm + arow_l) * FHB + (kk * 16 + acb * 8) * 2));

    float m0 = -1e30f, m1 = -1e30f, l0 = 0.f, l1 = 0.f;
    float oac[8][4];
    #pragma unroll
    for (int n = 0; n < 8; n++)
        #pragma unroll
        for (int c = 0; c < 4; c++) oac[n][c] = 0.f;

    for (int jt = 0; jt <= it; jt++) {
        int cur = jt & 1;
        if (jt + 1 <= it) {
            load_kv(jt + 1, 1 - cur);
            asm volatile("cp.async.wait_group 1;" ::: "memory");
        } else {
            asm volatile("cp.async.wait_group 0;" ::: "memory");
        }
        __syncthreads();

        uint32_t sK = sbK0 + cur * HT_BYTES;
        uint32_t sV = sbV0 + cur * HT_BYTES;

        float sac[8][4];
        #pragma unroll
        for (int n = 0; n < 8; n++)
            #pragma unroll
            for (int c = 0; c < 4; c++) sac[n][c] = 0.f;
        #pragma unroll
        for (int kk = 0; kk < 4; kk++) {
            uint32_t bfK[4][4];
            #pragma unroll
            for (int nb = 0; nb < 4; nb++)
                ldsm4(bfK[nb], sK + (uint32_t)((nb * 16 + brow_l) * FHB + (kk * 16 + bcb * 8) * 2));
            #pragma unroll
            for (int ni = 0; ni < 8; ni++) {
                int nb = ni >> 1, o = (ni & 1) * 2;
                mma_f16(sac[ni], qf[kk], bfK[nb][o], bfK[nb][o + 1]);
            }
        }

        #pragma unroll
        for (int ni = 0; ni < 8; ni++) {
            sac[ni][0] *= 0.125f; sac[ni][1] *= 0.125f;
            sac[ni][2] *= 0.125f; sac[ni][3] *= 0.125f;
        }
        if (jt == it) {
            #pragma unroll
            for (int ni = 0; ni < 8; ni++) {
                int cb = ni * 8 + 2 * tq;
                int r0 = wm + g, r1 = wm + g + 8;
                if (cb     > r0) sac[ni][0] = -1e30f;
                if (cb + 1 > r0) sac[ni][1] = -1e30f;
                if (cb     > r1) sac[ni][2] = -1e30f;
                if (cb + 1 > r1) sac[ni][3] = -1e30f;
            }
        }
        float a0 = -1e30f, a1 = -1e30f;
        #pragma unroll
        for (int ni = 0; ni < 8; ni++) {
            a0 = fmaxf(a0, fmaxf(sac[ni][0], sac[ni][1]));
            a1 = fmaxf(a1, fmaxf(sac[ni][2], sac[ni][3]));
        }
        a0 = fmaxf(a0, __shfl_xor_sync(0xffffffffu, a0, 1));
        a0 = fmaxf(a0, __shfl_xor_sync(0xffffffffu, a0, 2));
        a1 = fmaxf(a1, __shfl_xor_sync(0xffffffffu, a1, 1));
        a1 = fmaxf(a1, __shfl_xor_sync(0xffffffffu, a1, 2));
        float mn0 = fmaxf(m0, a0), mn1 = fmaxf(m1, a1);
        float al0 = __expf(m0 - mn0), al1 = __expf(m1 - mn1);
        m0 = mn0; m1 = mn1;
        l0 *= al0; l1 *= al1;
        #pragma unroll
        for (int ni = 0; ni < 8; ni++) {
            oac[ni][0] *= al0; oac[ni][1] *= al0;
            oac[ni][2] *= al1; oac[ni][3] *= al1;
        }
        float s0 = 0.f, s1 = 0.f;
        #pragma unroll
        for (int ni = 0; ni < 8; ni++) {
            __half2 hp0 = __floats2half2_rn(__expf(sac[ni][0] - mn0), __expf(sac[ni][1] - mn0));
            __half2 hp1 = __floats2half2_rn(__expf(sac[ni][2] - mn1), __expf(sac[ni][3] - mn1));
            s0 += __low2float(hp0) + __high2float(hp0);
            s1 += __low2float(hp1) + __high2float(hp1);
            int cb = ni * 8 + 2 * tq;
            *(__half2*)(Psp + (wm + g) * FPH + cb)     = hp0;
            *(__half2*)(Psp + (wm + g + 8) * FPH + cb) = hp1;
        }
        s0 += __shfl_xor_sync(0xffffffffu, s0, 1);
        s0 += __shfl_xor_sync(0xffffffffu, s0, 2);
        s1 += __shfl_xor_sync(0xffffffffu, s1, 1);
        s1 += __shfl_xor_sync(0xffffffffu, s1, 2);
        l0 += s0; l1 += s1;
        __syncwarp();

        #pragma unroll
        for (int jb = 0; jb < 4; jb++) {
            uint32_t pf[4];
            ldsm4(pf, sbP + (uint32_t)((wm + arow_l) * FHB + (jb * 16 + acb * 8) * 2));
            #pragma unroll
            for (int db = 0; db < 4; db++) {
                uint32_t vf[4];
                ldsm4t(vf, sV + (uint32_t)((jb * 16 + jrow) * FHB + (db * 16 + dcol) * 2));
                mma_f16(oac[db * 2],     pf, vf[0], vf[1]);
                mma_f16(oac[db * 2 + 1], pf, vf[2], vf[3]);
            }
        }
        __syncthreads();
    }

    float inv0 = 1.f / l0, inv1 = 1.f / l1;
    __half* od = ao + (size_t)(b * T_ + it * 64 + wm + g) * E_ + h * HD;
    #pragma unroll
    for (int nd = 0; nd < 8; nd++) {
        int cb = nd * 8 + 2 * tq;
        __half2 v0 = __floats2half2_rn(oac[nd][0] * inv0, oac[nd][1] * inv0);
        __half2 v1 = __floats2half2_rn(oac[nd][2] * inv1, oac[nd][3] * inv1);
        *(__half2*)(od + cb)                  = v0;
        *(__half2*)(od + (size_t)8 * E_ + cb) = v1;
    }
}

// ---------------- x = LayerNorm(in (+ res)) * g + b, all fp16 IO ----------------
__global__ void add_ln_kernel(const __half* __restrict__ in,
                              const __half* __restrict__ res,
                              const float* __restrict__ g,
                              const float* __restrict__ bb,
                              __half* __restrict__ out) {
    int row = blockIdx.x;
    int t = threadIdx.x;
    uint2 ui = ((const uint2*)(in + (size_t)row * E_))[t];
    __half2 i0 = *(__half2*)&ui.x, i1 = *(__half2*)&ui.y;
    float4 v;
    v.x = __low2float(i0); v.y = __high2float(i0);
    v.z = __low2float(i1); v.w = __high2float(i1);
    if (res) {
        uint2 ur = ((const uint2*)(res + (size_t)row * E_))[t];
        __half2 r0 = *(__half2*)&ur.x, r1 = *(__half2*)&ur.y;
        v.x += __low2float(r0); v.y += __high2float(r0);
        v.z += __low2float(r1); v.w += __high2float(r1);
    }
    float s  = v.x + v.y + v.z + v.w;
    float s2 = v.x * v.x + v.y * v.y + v.z * v.z + v.w * v.w;

    __shared__ float sh[16];
    s = warpSum(s); s2 = warpSum(s2);
    int w = t >> 5, lane = t & 31;
    if (lane == 0) { sh[w] = s; sh[w + 8] = s2; }
    __syncthreads();
    if (w == 0) {
        float a  = (lane < 8) ? sh[lane] : 0.f;
        a = warpSum(a);
        float a2 = (lane < 8) ? sh[lane + 8] : 0.f;
        a2 = warpSum(a2);
        if (lane == 0) { sh[0] = a; sh[8] = a2; }
    }
    __syncthreads();
    float mean = sh[0] * (1.f / E_);
    float var  = sh[8] * (1.f / E_) - mean * mean;
    float rstd = rsqrtf(var + 1e-5f);

    float4 gv = ((const float4*)g)[t];
    float4 bv = ((const float4*)bb)[t];
    float4 o;
    o.x = (v.x - mean) * rstd * gv.x + bv.x;
    o.y = (v.y - mean) * rstd * gv.y + bv.y;
    o.z = (v.z - mean) * rstd * gv.z + bv.z;
    o.w = (v.w - mean) * rstd * gv.w + bv.w;

    __half2 h0 = __floats2half2_rn(o.x, o.y);
    __half2 h1 = __floats2half2_rn(o.z, o.w);
    uint2 u; u.x = *(uint32_t*)&h0; u.y = *(uint32_t*)&h1;
    ((uint2*)(out + (size_t)row * E_))[t] = u;
}

// ---------------- host launch ----------------
extern "C" void kernel_launch(void* const* d_in, const int* in_sizes, int n_in,
                              void* d_out, int out_size) {
    const int*   idx   = (const int*)  d_in[0];
    const float* tok   = (const float*)d_in[1];
    const float* pos   = (const float*)d_in[2];
    const float* Wq    = (const float*)d_in[3];
    const float* bq    = (const float*)d_in[4];
    const float* Wk    = (const float*)d_in[5];
    const float* bk    = (const float*)d_in[6];
    const float* Wv    = (const float*)d_in[7];
    const float* bv    = (const float*)d_in[8];
    const float* Wo    = (const float*)d_in[9];
    const float* bo    = (const float*)d_in[10];
    const float* W1    = (const float*)d_in[11];
    const float* b1    = (const float*)d_in[12];
    const float* W2    = (const float*)d_in[13];
    const float* b2    = (const float*)d_in[14];
    const float* ln1g  = (const float*)d_in[15];
    const float* ln1b  = (const float*)d_in[16];
    const float* ln2g  = (const float*)d_in[17];
    const float* ln2b  = (const float*)d_in[18];
    const float* lnfg  = (const float*)d_in[19];
    const float* lnfb  = (const float*)d_in[20];
    const float* Whead = (const float*)d_in[21];
    const float* bhead = (const float*)d_in[22];
    float* out = (float*)d_out;

    float *bqkv;
    __half *x, *qkvh, *tmp, *ffr, *wt;
    cudaGetSymbolAddress((void**)&x,    g_x);
    cudaGetSymbolAddress((void**)&qkvh, g_qkvh);
    cudaGetSymbolAddress((void**)&tmp,  g_tmp);
    cudaGetSymbolAddress((void**)&ffr,  g_ffr);
    cudaGetSymbolAddress((void**)&bqkv, g_bqkv);
    cudaGetSymbolAddress((void**)&wt,   g_wt);

    __half* ao = ffr;    // attn-out scratch (front BT*E of ffr; consumed before FF1 writes)

    cudaFuncSetAttribute(h16_gemm_kernel<0,0>,
                         cudaFuncAttributeMaxDynamicSharedMemorySize, GSM);
    cudaFuncSetAttribute(h16_gemm_kernel<0,2>,
                         cudaFuncAttributeMaxDynamicSharedMemorySize, GSM);
    cudaFuncSetAttribute(h16_gemm_kernel<1,2>,
                         cudaFuncAttributeMaxDynamicSharedMemorySize, GSM);
    cudaFuncSetAttribute(flash_kernel,
                         cudaFuncAttributeMaxDynamicSharedMemorySize, FSMEM);

    tconv_kernel<<<dim3(E_ / 32,  E_ / 128,  L_), 256>>>(Wq, wt + OQKV,             E_, E_, 3 * SZ_EE);
    tconv_kernel<<<dim3(E_ / 32,  E_ / 128,  L_), 256>>>(Wk, wt + OQKV + SZ_EE,     E_, E_, 3 * SZ_EE);
    tconv_kernel<<<dim3(E_ / 32,  E_ / 128,  L_), 256>>>(Wv, wt + OQKV + 2 * SZ_EE, E_, E_, 3 * SZ_EE);
    tconv_kernel<<<dim3(E_ / 32,  E_ / 128,  L_), 256>>>(Wo, wt + OWO,  E_,  E_,  SZ_EE);
    tconv_kernel<<<dim3(FF_ / 32, E_ / 128,  L_), 256>>>(W1, wt + OW1,  E_,  FF_, (size_t)E_ * FF_);
    tconv_kernel<<<dim3(E_ / 32,  FF_ / 128, L_), 256>>>(W2, wt + OW2,  FF_, E_,  (size_t)E_ * FF_);
    tconv_kernel<<<dim3(V_ / 32,  E_ / 128,  1 ), 256>>>(Whead, wt + OHEAD, E_, V_, 0);
    pack_bias_kernel<<<dim3(12, L_), 256>>>(bq, bk, bv, bqkv);

    embed_kernel<<<BT, 256>>>(idx, tok, pos, x);

    dim3 gQKV(E3 / 128, BT / 128);
    dim3 gEE(E_ / 128, BT / 128);
    dim3 gEF(FF_ / 128, BT / 128);
    dim3 gHead(V_ / 128, BT / 128);

    for (int l = 0; l < L_; l++) {
        h16_gemm_kernel<0,2><<<gQKV, 256, GSM>>>(
            x, wt + OQKV + (size_t)l * 3 * SZ_EE, bqkv + l * E3,
            nullptr, qkvh, BT, E3, E_);

        flash_kernel<<<dim3(16, B_ * H_), 128, FSMEM>>>(qkvh, ao);

        h16_gemm_kernel<0,2><<<gEE, 256, GSM>>>(
            ao, wt + OWO + (size_t)l * SZ_EE, bo + l * E_,
            nullptr, tmp, BT, E_, E_);
        add_ln_kernel<<<BT, 256>>>(tmp, x, ln1g + l * E_, ln1b + l * E_, x);

        h16_gemm_kernel<1,2><<<gEF, 256, GSM>>>(
            x, wt + OW1 + (size_t)l * E_ * FF_, b1 + l * FF_,
            nullptr, ffr, BT, FF_, E_);
        h16_gemm_kernel<0,2><<<gEE, 256, GSM>>>(
            ffr, wt + OW2 + (size_t)l * E_ * FF_, b2 + l * E_,
            nullptr, tmp, BT, E_, FF_);
        add_ln_kernel<<<BT, 256>>>(tmp, x, ln2g + l * E_, ln2b + l * E_, x);
    }

    add_ln_kernel<<<BT, 256>>>(x, nullptr, lnfg, lnfb, x);
    h16_gemm_kernel<0,0><<<gHead, 256, GSM>>>(
        x, wt + OHEAD, bhead, out, nullptr, BT, V_, E_);
}